// round 13
// baseline (speedup 1.0000x reference)
#include <cuda_runtime.h>
#include <cuda_fp16.h>
#include <math.h>
#include <stdint.h>

// ---------------- problem constants ----------------
#define BB 2
#define SS 2048
#define HH 768
#define NHH 12
#define DD 64
#define LL 4
#define CW 128
#define GT 16
#define PP 128
#define NLC 3
#define FF (4*HH)
#define MROWS (BB*SS)
#define QKVW (3*HH)   // 2304

// ---------------- scratch ----------------
__device__ float  g_x   [MROWS*HH];
__device__ float  g_t   [MROWS*HH];
__device__ __half g_qkvh[MROWS*QKVW];
__device__ __half g_xh  [MROWS*HH];
__device__ __half g_o16 [MROWS*HH];
__device__ __half g_h16 [MROWS*FF];
__device__ float  g_bqkv[LL*QKVW];
#define WQKVOFF 0
#define WOOFF   (3*LL*HH*HH)
#define WF1OFF  (4*LL*HH*HH)
#define WF2OFF  (4*LL*HH*HH + LL*HH*FF)
#define WTOTAL  (4*LL*HH*HH + 2*LL*HH*FF)
__device__ __half g_wbuf[WTOTAL];

// ---------------- fp32 -> fp16 bulk convert ----------------
__global__ void f2h_kernel(const float* __restrict__ s, __half* __restrict__ d, int n)
{
    int i = (blockIdx.x * 256 + threadIdx.x) * 8;
    if (i >= n) return;
    float4 v0 = *(const float4*)&s[i];
    float4 v1 = *(const float4*)&s[i + 4];
    __half2 h0 = __floats2half2_rn(v0.x, v0.y);
    __half2 h1 = __floats2half2_rn(v0.z, v0.w);
    __half2 h2 = __floats2half2_rn(v1.x, v1.y);
    __half2 h3 = __floats2half2_rn(v1.z, v1.w);
    uint4 o;
    o.x = *reinterpret_cast<unsigned*>(&h0);
    o.y = *reinterpret_cast<unsigned*>(&h1);
    o.z = *reinterpret_cast<unsigned*>(&h2);
    o.w = *reinterpret_cast<unsigned*>(&h3);
    *(uint4*)&d[i] = o;
}

// ---------------- pack Wq|Wk|Wv -> [L][H][2304] fp16, scale q by 0.125 ----------------
__global__ void pack_qkv_kernel(const float* __restrict__ Wq, const float* __restrict__ Wk,
                                const float* __restrict__ Wv, __half* __restrict__ dst)
{
    long i = ((long)blockIdx.x * 256 + threadIdx.x) * 8;
    if (i >= (long)LL * HH * QKVW) return;
    int l   = (int)(i / (HH * QKVW));
    int rem = (int)(i - (long)l * HH * QKVW);
    int k   = rem / QKVW;
    int j   = rem - k * QKVW;
    int seg = j / HH;
    int jj  = j - seg * HH;
    const float* src = (seg == 0 ? Wq : seg == 1 ? Wk : Wv) + ((long)l * HH + k) * HH + jj;
    float sc = (seg == 0) ? 0.125f : 1.0f;
    float4 v0 = *(const float4*)&src[0];
    float4 v1 = *(const float4*)&src[4];
    __half2 h0 = __floats2half2_rn(v0.x * sc, v0.y * sc);
    __half2 h1 = __floats2half2_rn(v0.z * sc, v0.w * sc);
    __half2 h2 = __floats2half2_rn(v1.x * sc, v1.y * sc);
    __half2 h3 = __floats2half2_rn(v1.z * sc, v1.w * sc);
    uint4 o;
    o.x = *reinterpret_cast<unsigned*>(&h0);
    o.y = *reinterpret_cast<unsigned*>(&h1);
    o.z = *reinterpret_cast<unsigned*>(&h2);
    o.w = *reinterpret_cast<unsigned*>(&h3);
    *(uint4*)&dst[i] = o;
}

__global__ void pack_bqkv_kernel(const float* __restrict__ bq, const float* __restrict__ bk,
                                 const float* __restrict__ bv, float* __restrict__ dst)
{
    int i = blockIdx.x * 256 + threadIdx.x;
    if (i >= LL * QKVW) return;
    int l = i / QKVW;
    int j = i - l * QKVW;
    int seg = j / HH;
    int jj  = j - seg * HH;
    dst[i] = (seg == 0 ? bq[l * HH + jj] * 0.125f : seg == 1 ? bk[l * HH + jj] : bv[l * HH + jj]);
}

// ---------------- embedding gather ----------------
__global__ void embed_kernel(const int* __restrict__ ids,
                             const float* __restrict__ emb,
                             float* __restrict__ x, __half* __restrict__ xh)
{
    int idx = blockIdx.x * blockDim.x + threadIdx.x;
    if (idx >= MROWS * HH) return;
    int tok = idx / HH;
    int d   = idx - tok * HH;
    float e = emb[(long)ids[tok] * HH + d];
    x[idx]  = e;
    xh[idx] = __float2half(e);
}

// ---------------- fp16 tensor-core GEMM, CTA 128x128, K-stage 32, ldmatrix A+B ----------------
// mode 0: Ch = AW+b (fp16); mode 1: Cf = AW+b+R; mode 2: Ch = gelu(AW+b)
#define GM 128
#define GN 128
#define NST 4
#define APITCH 80                 // bytes per A row (64 used + 16 pad); 80/4=20 banks -> conflict-free
#define A_STAGE (GM*APITCH)       // 10240 B
#define B_STAGE (32*256)          // 8192 B
#define GEMM_SMEM (NST*(A_STAGE+B_STAGE))  // 73728 B

__device__ __forceinline__ void mma_f16(float* d, const unsigned* a, const unsigned* b) {
    asm volatile(
        "mma.sync.aligned.m16n8k16.row.col.f32.f16.f16.f32 "
        "{%0,%1,%2,%3}, {%4,%5,%6,%7}, {%8,%9}, {%0,%1,%2,%3};\n"
        : "+f"(d[0]), "+f"(d[1]), "+f"(d[2]), "+f"(d[3])
        : "r"(a[0]), "r"(a[1]), "r"(a[2]), "r"(a[3]),
          "r"(b[0]), "r"(b[1]));
}

__device__ __forceinline__ void cp16(unsigned smem, const void* g) {
    asm volatile("cp.async.cg.shared.global [%0], [%1], 16;\n" :: "r"(smem), "l"(g));
}

__global__ void __launch_bounds__(256, 2)
gemm16_kernel(const __half* __restrict__ A, const __half* __restrict__ W,
              const float* __restrict__ bias, const float* __restrict__ R,
              float* __restrict__ Cf, __half* __restrict__ Ch,
              int M, int N, int K, int mode)
{
    extern __shared__ __align__(16) char dynsmem[];
    const unsigned smem0 = (unsigned)__cvta_generic_to_shared(dynsmem);
    const unsigned a0 = smem0;                    // NST * A_STAGE
    const unsigned b0 = smem0 + NST * A_STAGE;    // NST * B_STAGE

    const int tid  = threadIdx.x;
    const int w    = tid >> 5;
    const int lane = tid & 31;
    const int gid  = lane >> 2;
    const int tig  = lane & 3;
    const int wm   = (w >> 1) * 32;
    const int wn   = (w & 1) * 64;
    const int row0 = blockIdx.y * GM;
    const int col0 = blockIdx.x * GN;

    // A staging: row ar = tid>>1, 16B chunks {2*ac, 2*ac+1} of the 64B k32 row
    const int ar = tid >> 1;
    const int ac = tid & 1;
    // B staging: rows bk and bk+16, chunk bc (swizzled by row&7)
    const int bk = tid >> 4;
    const int bc = tid & 15;
    const int bcs = bc ^ (bk & 7);

    const long arow_base = (long)(row0 + ar) * K;
    const long brow_col  = (long)col0 + bc * 8;

    // ldmatrix A lane mapping
    const int asel  = lane >> 3;
    const int amloc = (lane & 7) + (asel & 1) * 8;
    const int akh   = asel >> 1;          // k8-half within substep
    // ldmatrix B lane mapping
    const int lsel = lane >> 3;
    const int lk   = (lsel & 1) * 8 + (lane & 7);
    const int lnc  = (lsel >> 1);

    float acc[2][8][4];
#pragma unroll
    for (int mt = 0; mt < 2; mt++)
#pragma unroll
        for (int nt = 0; nt < 8; nt++)
#pragma unroll
            for (int u = 0; u < 4; u++) acc[mt][nt][u] = 0.f;

    const int nk = K / 32;

    auto load_stage = [&](int kt) {
        const int s = kt & 3;
        const unsigned adst = a0 + s * A_STAGE + ar * APITCH;
        const __half* ag = &A[arow_base + kt * 32];
        cp16(adst + (2 * ac)     * 16, ag + (2 * ac)     * 8);
        cp16(adst + (2 * ac + 1) * 16, ag + (2 * ac + 1) * 8);
        const unsigned bdst = b0 + s * B_STAGE;
        cp16(bdst + bk * 256 + bcs * 16,         &W[(long)(kt * 32 + bk)      * N + brow_col]);
        cp16(bdst + (bk + 16) * 256 + bcs * 16,  &W[(long)(kt * 32 + bk + 16) * N + brow_col]);
        asm volatile("cp.async.commit_group;\n");
    };

    load_stage(0);
    if (nk > 1) load_stage(1); else asm volatile("cp.async.commit_group;\n");
    if (nk > 2) load_stage(2); else asm volatile("cp.async.commit_group;\n");

    for (int kt = 0; kt < nk; kt++) {
        const int s = kt & 3;
        asm volatile("cp.async.wait_group 1;\n" ::: "memory");
        __syncthreads();

        if (kt + 3 < nk) load_stage(kt + 3);
        else asm volatile("cp.async.commit_group;\n");

        const unsigned astage = a0 + s * A_STAGE;
        const unsigned bstage = b0 + s * B_STAGE;

#pragma unroll
        for (int u = 0; u < 2; u++) {          // two k16 substeps
            unsigned afr[2][4];
#pragma unroll
            for (int mt = 0; mt < 2; mt++) {
                unsigned addr = astage + (wm + mt * 16 + amloc) * APITCH + u * 32 + akh * 16;
                asm volatile(
                    "ldmatrix.sync.aligned.m8n8.x4.shared.b16 {%0,%1,%2,%3}, [%4];"
                    : "=r"(afr[mt][0]), "=r"(afr[mt][1]), "=r"(afr[mt][2]), "=r"(afr[mt][3])
                    : "r"(addr));
            }
            unsigned bfr[8][2];
#pragma unroll
            for (int ntp = 0; ntp < 4; ntp++) {
                int ncg = (wn >> 3) + ntp * 2 + lnc;
                int chunk = ncg ^ (lk & 7);
                unsigned addr = bstage + (u * 16 + lk) * 256 + chunk * 16;
                unsigned r0, r1, r2, r3;
                asm volatile(
                    "ldmatrix.sync.aligned.m8n8.x4.trans.shared.b16 {%0,%1,%2,%3}, [%4];"
                    : "=r"(r0), "=r"(r1), "=r"(r2), "=r"(r3) : "r"(addr));
                bfr[ntp * 2    ][0] = r0;
                bfr[ntp * 2    ][1] = r1;
                bfr[ntp * 2 + 1][0] = r2;
                bfr[ntp * 2 + 1][1] = r3;
            }
#pragma unroll
            for (int mt = 0; mt < 2; mt++)
#pragma unroll
                for (int nt = 0; nt < 8; nt++)
                    mma_f16(acc[mt][nt], afr[mt], bfr[nt]);
        }
    }

    // ---- epilogue ----
#pragma unroll
    for (int nt = 0; nt < 8; nt++) {
        const int cc = col0 + wn + nt * 8 + 2 * tig;
        float2 bv = *(const float2*)&bias[cc];
#pragma unroll
        for (int mt = 0; mt < 2; mt++) {
            int r0 = row0 + wm + mt * 16 + gid;
#pragma unroll
            for (int half_ = 0; half_ < 2; half_++) {
                int rr = r0 + half_ * 8;
                float vx = acc[mt][nt][half_ * 2 + 0] + bv.x;
                float vy = acc[mt][nt][half_ * 2 + 1] + bv.y;
                if (mode == 0) {
                    *(__half2*)&Ch[(long)rr * N + cc] = __floats2half2_rn(vx, vy);
                } else if (mode == 1) {
                    float2 rrv = *(const float2*)&R[(long)rr * N + cc];
                    *(float2*)&Cf[(long)rr * N + cc] = make_float2(vx + rrv.x, vy + rrv.y);
                } else {
                    float t0 = vx, t1 = vy;
                    vx = 0.5f * t0 * (1.f + tanhf(0.7978845608028654f * (t0 + 0.044715f * t0 * t0 * t0)));
                    vy = 0.5f * t1 * (1.f + tanhf(0.7978845608028654f * (t1 + 0.044715f * t1 * t1 * t1)));
                    *(__half2*)&Ch[(long)rr * N + cc] = __floats2half2_rn(vx, vy);
                }
            }
        }
    }
}

// ---------------- layernorm over H=768 ----------------
__global__ void __launch_bounds__(256)
ln_kernel(const float* __restrict__ in, const float* __restrict__ g,
          const float* __restrict__ b, float* __restrict__ out, __half* __restrict__ outh)
{
    const int row = blockIdx.x;
    const float* x = in + (long)row * HH;
    float v0[3];
    float s = 0.f, s2 = 0.f;
#pragma unroll
    for (int i = 0; i < 3; i++) {
        float t = x[threadIdx.x + i * 256];
        v0[i] = t; s += t; s2 += t * t;
    }
#pragma unroll
    for (int o = 16; o > 0; o >>= 1) {
        s  += __shfl_xor_sync(0xffffffffu, s, o);
        s2 += __shfl_xor_sync(0xffffffffu, s2, o);
    }
    __shared__ float red0[8], red1[8];
    int w = threadIdx.x >> 5;
    if ((threadIdx.x & 31) == 0) { red0[w] = s; red1[w] = s2; }
    __syncthreads();
    if (threadIdx.x < 32) {
        s  = (threadIdx.x < 8) ? red0[threadIdx.x] : 0.f;
        s2 = (threadIdx.x < 8) ? red1[threadIdx.x] : 0.f;
#pragma unroll
        for (int o = 4; o > 0; o >>= 1) {
            s  += __shfl_xor_sync(0xffffffffu, s, o);
            s2 += __shfl_xor_sync(0xffffffffu, s2, o);
        }
        if (threadIdx.x == 0) { red0[0] = s; red1[0] = s2; }
    }
    __syncthreads();
    float mean = red0[0] * (1.f / HH);
    float var  = red1[0] * (1.f / HH) - mean * mean;
    float rstd = rsqrtf(var + 1e-5f);
#pragma unroll
    for (int i = 0; i < 3; i++) {
        int c = threadIdx.x + i * 256;
        float val = (v0[i] - mean) * rstd * g[c] + b[c];
        out [(long)row * HH + c] = val;
        outh[(long)row * HH + c] = __float2half(val);
    }
}

// ---------------- banded attention via mma (fp16 qkv) ----------------
__global__ void __launch_bounds__(256)
band_attn_kernel(const __half* __restrict__ qkv, __half* __restrict__ o)
{
    const int n = blockIdx.x, h = blockIdx.y, b = blockIdx.z;
    const int tid  = threadIdx.x;
    const int w    = tid >> 5;
    const int lane = tid & 31;
    const int gid  = lane >> 2;
    const int tig  = lane & 3;

    __shared__ __align__(16) char smem[2][2][64 * 128];
    const unsigned smem_base = (unsigned)__cvta_generic_to_shared(&smem[0][0][0]);

    const int s_q0 = n * CW + w * 16 + gid;
    const int s_q1 = s_q0 + 8;

    unsigned qf[4][4];
    {
        const __half* q0 = qkv + ((long)(b * SS + s_q0) * QKVW + h * DD);
        const __half* q1 = qkv + ((long)(b * SS + s_q1) * QKVW + h * DD);
#pragma unroll
        for (int kk = 0; kk < 4; kk++) {
            int d0 = kk * 16 + 2 * tig;
            qf[kk][0] = *(const unsigned*)(q0 + d0);
            qf[kk][1] = *(const unsigned*)(q1 + d0);
            qf[kk][2] = *(const unsigned*)(q0 + d0 + 8);
            qf[kk][3] = *(const unsigned*)(q1 + d0 + 8);
        }
    }

    float m0 = -1e30f, m1 = -1e30f, l0 = 0.f, l1 = 0.f;
    float accO[8][4];
#pragma unroll
    for (int dt = 0; dt < 8; dt++)
#pragma unroll
        for (int u = 0; u < 4; u++) accO[dt][u] = 0.f;

    auto fill = [&](int t) {
        const int buf = t & 1;
#pragma unroll
        for (int i = 0; i < 4; i++) {
            int g = tid + i * 256;
            int tensor = g >> 9;
            int within = g & 511;
            int row = within >> 3;
            int c   = within & 7;
            int p  = (t == 6) ? row : (n * CW - CW + t * 64 + row);
            int pc = min(max(p, 0), SS - 1);
            const __half* src = qkv + ((long)(b * SS + pc) * QKVW + (tensor ? 2 * HH : HH) + h * DD + c * 8);
            unsigned dst = smem_base + buf * 16384 + tensor * 8192 + row * 128 + (((unsigned)(c ^ (row & 7))) << 4);
            cp16(dst, src);
        }
        asm volatile("cp.async.commit_group;\n");
    };

    fill(0);

    for (int t = 0; t < 7; t++) {
        const int buf = t & 1;
        if (t + 1 < 7) {
            fill(t + 1);
            asm volatile("cp.async.wait_group 1;\n" ::: "memory");
        } else {
            asm volatile("cp.async.wait_group 0;\n" ::: "memory");
        }
        __syncthreads();

        const unsigned kb = smem_base + buf * 16384;
        const unsigned vb = kb + 8192;

        float s[8][4];
#pragma unroll
        for (int ng = 0; ng < 8; ng++)
#pragma unroll
            for (int u = 0; u < 4; u++) s[ng][u] = 0.f;

#pragma unroll
        for (int ng = 0; ng < 8; ng++) {
#pragma unroll
            for (int kp = 0; kp < 2; kp++) {
                int row = ng * 8 + (lane & 7);
                int ci  = kp * 4 + (lane >> 3);
                unsigned addr = kb + row * 128 + (((unsigned)(ci ^ (row & 7))) << 4);
                unsigned r0, r1, r2, r3;
                asm volatile(
                    "ldmatrix.sync.aligned.m8n8.x4.shared.b16 {%0,%1,%2,%3}, [%4];"
                    : "=r"(r0), "=r"(r1), "=r"(r2), "=r"(r3) : "r"(addr));
                unsigned bf0[2] = {r0, r1};
                unsigned bf1[2] = {r2, r3};
                mma_f16(s[ng], qf[kp * 2],     bf0);
                mma_f16(s[ng], qf[kp * 2 + 1], bf1);
            }
        }

        const int p00 = (t == 6) ? 0 : (n * CW - CW + t * 64);
#pragma unroll
        for (int ng = 0; ng < 8; ng++) {
            int k0 = ng * 8 + 2 * tig;
            int p0v = p00 + k0;
            int p1v = p0v + 1;
            bool v00, v01, v10, v11;
            if (t == 6) {
                v00 = v10 = (k0 < GT);
                v01 = v11 = (k0 + 1 < GT);
            } else {
                bool base0 = (p0v >= GT) && (p0v < SS);
                bool base1 = (p1v >= GT) && (p1v < SS);
                v00 = base0 && (abs(p0v - s_q0) <= CW);
                v10 = base0 && (abs(p0v - s_q1) <= CW);
                v01 = base1 && (abs(p1v - s_q0) <= CW);
                v11 = base1 && (abs(p1v - s_q1) <= CW);
            }
            if (!v00) s[ng][0] = -1e30f;
            if (!v01) s[ng][1] = -1e30f;
            if (!v10) s[ng][2] = -1e30f;
            if (!v11) s[ng][3] = -1e30f;
        }

        float t0 = -1e30f, t1 = -1e30f;
#pragma unroll
        for (int ng = 0; ng < 8; ng++) {
            t0 = fmaxf(t0, fmaxf(s[ng][0], s[ng][1]));
            t1 = fmaxf(t1, fmaxf(s[ng][2], s[ng][3]));
        }
        t0 = fmaxf(t0, __shfl_xor_sync(0xffffffffu, t0, 1));
        t0 = fmaxf(t0, __shfl_xor_sync(0xffffffffu, t0, 2));
        t1 = fmaxf(t1, __shfl_xor_sync(0xffffffffu, t1, 1));
        t1 = fmaxf(t1, __shfl_xor_sync(0xffffffffu, t1, 2));

        float mn0 = fmaxf(m0, t0), mn1 = fmaxf(m1, t1);
        float al0 = __expf(m0 - mn0), al1 = __expf(m1 - mn1);
        l0 *= al0; l1 *= al1;
#pragma unroll
        for (int dt = 0; dt < 8; dt++) {
            accO[dt][0] *= al0; accO[dt][1] *= al0;
            accO[dt][2] *= al1; accO[dt][3] *= al1;
        }

        unsigned ph[8][2];
#pragma unroll
        for (int ng = 0; ng < 8; ng++) {
            float p0 = (s[ng][0] < -1e29f) ? 0.f : __expf(s[ng][0] - mn0);
            float p1 = (s[ng][1] < -1e29f) ? 0.f : __expf(s[ng][1] - mn0);
            float p2 = (s[ng][2] < -1e29f) ? 0.f : __expf(s[ng][2] - mn1);
            float p3 = (s[ng][3] < -1e29f) ? 0.f : __expf(s[ng][3] - mn1);
            l0 += p0 + p1;
            l1 += p2 + p3;
            __half2 h01 = __floats2half2_rn(p0, p1);
            __half2 h23 = __floats2half2_rn(p2, p3);
            ph[ng][0] = *reinterpret_cast<unsigned*>(&h01);
            ph[ng][1] = *reinterpret_cast<unsigned*>(&h23);
        }
        m0 = mn0; m1 = mn1;

        const int lsel = lane >> 3;
        const int lk   = (lsel & 1) * 8 + (lane & 7);
        const int lnc  = lsel >> 1;
#pragma unroll
        for (int kk = 0; kk < 4; kk++) {
            unsigned af[4] = { ph[2 * kk][0], ph[2 * kk][1], ph[2 * kk + 1][0], ph[2 * kk + 1][1] };
#pragma unroll
            for (int dp = 0; dp < 4; dp++) {
                int row = kk * 16 + lk;
                int ci  = (dp * 2 + lnc) ^ (row & 7);
                unsigned addr = vb + row * 128 + (((unsigned)ci) << 4);
                unsigned r0, r1, r2, r3;
                asm volatile(
                    "ldmatrix.sync.aligned.m8n8.x4.trans.shared.b16 {%0,%1,%2,%3}, [%4];"
                    : "=r"(r0), "=r"(r1), "=r"(r2), "=r"(r3) : "r"(addr));
                unsigned b0[2] = {r0, r1};
                unsigned b1[2] = {r2, r3};
                mma_f16(accO[dp * 2],     af, b0);
                mma_f16(accO[dp * 2 + 1], af, b1);
            }
        }
        __syncthreads();
    }

    l0 += __shfl_xor_sync(0xffffffffu, l0, 1);
    l0 += __shfl_xor_sync(0xffffffffu, l0, 2);
    l1 += __shfl_xor_sync(0xffffffffu, l1, 1);
    l1 += __shfl_xor_sync(0xffffffffu, l1, 2);
    float i0 = 1.f / l0, i1 = 1.f / l1;

    __half* o0 = o + ((long)(b * SS + s_q0) * HH + h * DD);
    __half* o1 = o + ((long)(b * SS + s_q1) * HH + h * DD);
#pragma unroll
    for (int dt = 0; dt < 8; dt++) {
        int d0 = dt * 8 + 2 * tig;
        *(__half2*)(o0 + d0) = __floats2half2_rn(accO[dt][0] * i0, accO[dt][1] * i0);
        *(__half2*)(o1 + d0) = __floats2half2_rn(accO[dt][2] * i1, accO[dt][3] * i1);
    }
}

// ---------------- global-query attention (fp16 qkv) ----------------
__global__ void __launch_bounds__(128)
glob_attn_kernel(const __half* __restrict__ qkv, __half* __restrict__ o)
{
    const int g = blockIdx.x, h = blockIdx.y, b = blockIdx.z;
    const int tid = threadIdx.x;

    __shared__ float qs[DD];
    __shared__ float sc[SS];
    __shared__ float red[4];
    __shared__ float part[4][DD];

    if (tid < DD) qs[tid] = __half2float(qkv[(long)(b * SS + g) * QKVW + h * DD + tid]);
    __syncthreads();

    float lm = -1e30f;
    for (int s = tid; s < SS; s += 128) {
        const __half* kr = qkv + ((long)(b * SS + s) * QKVW + HH + h * DD);
        float acc = 0.f;
#pragma unroll
        for (int c = 0; c < 8; c++) {
            uint4 raw = *(const uint4*)(kr + c * 8);
            __half2* hp = (__half2*)&raw;
#pragma unroll
            for (int u = 0; u < 4; u++) {
                float2 kf = __half22float2(hp[u]);
                acc += qs[c * 8 + 2 * u] * kf.x + qs[c * 8 + 2 * u + 1] * kf.y;
            }
        }
        sc[s] = acc;
        lm = fmaxf(lm, acc);
    }
#pragma unroll
    for (int off = 16; off > 0; off >>= 1)
        lm = fmaxf(lm, __shfl_xor_sync(0xffffffffu, lm, off));
    if ((tid & 31) == 0) red[tid >> 5] = lm;
    __syncthreads();
    float m = fmaxf(fmaxf(red[0], red[1]), fmaxf(red[2], red[3]));

    float ls = 0.f;
    for (int s = tid; s < SS; s += 128) {
        float e = __expf(sc[s] - m);
        sc[s] = e;
        ls += e;
    }
#pragma unroll
    for (int off = 16; off > 0; off >>= 1)
        ls += __shfl_xor_sync(0xffffffffu, ls, off);
    __syncthreads();
    if ((tid & 31) == 0) red[tid >> 5] = ls;
    __syncthreads();
    float l = red[0] + red[1] + red[2] + red[3];

    const int d2  = (tid & 31) * 2;
    const int grp = tid >> 5;
    float2 acc2 = make_float2(0.f, 0.f);
    const __half* vp = qkv + ((long)(b * SS) * QKVW + 2 * HH + h * DD + d2);
    const int s0 = grp * (SS / 4);
    for (int s = s0; s < s0 + SS / 4; s++) {
        __half2 hv = *(const __half2*)(vp + (long)s * QKVW);
        float2 f = __half22float2(hv);
        acc2.x += sc[s] * f.x;
        acc2.y += sc[s] * f.y;
    }
    part[grp][d2]     = acc2.x;
    part[grp][d2 + 1] = acc2.y;
    __syncthreads();
    if (tid < DD) {
        float inv = 1.f / l;
        float v = (part[0][tid] + part[1][tid] + part[2][tid] + part[3][tid]) * inv;
        o[(long)(b * SS + g) * HH + h * DD + tid] = __float2half(v);
    }
}

// ---------------- pair gather + classifier head ----------------
__global__ void __launch_bounds__(128)
head_kernel(const float* __restrict__ x, const int* __restrict__ pairs,
            const float* __restrict__ Wh, const float* __restrict__ bh,
            float* __restrict__ out)
{
    const int bp = blockIdx.x;
    const int b = bp >> 7;
    const int i = pairs[bp * 2 + 0];
    const int j = pairs[bp * 2 + 1];
    const float* xi = x + (long)(b * SS + i) * HH;
    const float* xj = x + (long)(b * SS + j) * HH;

    float acc[NLC] = {0.f, 0.f, 0.f};
    for (int d = threadIdx.x; d < 2 * HH; d += 128) {
        float e = (d < HH) ? xi[d] : xj[d - HH];
        acc[0] += e * Wh[d * NLC + 0];
        acc[1] += e * Wh[d * NLC + 1];
        acc[2] += e * Wh[d * NLC + 2];
    }
#pragma unroll
    for (int o = 16; o > 0; o >>= 1) {
#pragma unroll
        for (int c = 0; c < NLC; c++)
            acc[c] += __shfl_xor_sync(0xffffffffu, acc[c], o);
    }
    __shared__ float sm[NLC][4];
    int w = threadIdx.x >> 5;
    if ((threadIdx.x & 31) == 0) {
#pragma unroll
        for (int c = 0; c < NLC; c++) sm[c][w] = acc[c];
    }
    __syncthreads();
    if (threadIdx.x < NLC) {
        float s = sm[threadIdx.x][0] + sm[threadIdx.x][1] + sm[threadIdx.x][2] + sm[threadIdx.x][3];
        out[bp * NLC + threadIdx.x] = s + bh[threadIdx.x];
    }
}

// ---------------- host orchestration ----------------
extern "C" void kernel_launch(void* const* d_in, const int* in_sizes, int n_in,
                              void* d_out, int out_size)
{
    const int*   input_ids    = (const int*)  d_in[0];
    const int*   pair_indices = (const int*)  d_in[1];
    const float* emb          = (const float*)d_in[2];
    const float* Wq  = (const float*)d_in[3];
    const float* bq  = (const float*)d_in[4];
    const float* Wk  = (const float*)d_in[5];
    const float* bk  = (const float*)d_in[6];
    const float* Wv  = (const float*)d_in[7];
    const float* bv  = (const float*)d_in[8];
    const float* Wo  = (const float*)d_in[9];
    const float* bo  = (const float*)d_in[10];
    const float* ln1g = (const float*)d_in[11];
    const float* ln1b = (const float*)d_in[12];
    const float* Wf1 = (const float*)d_in[13];
    const float* bf1 = (const float*)d_in[14];
    const float* Wf2 = (const float*)d_in[15];
    const float* bf2 = (const float*)d_in[16];
    const float* ln2g = (const float*)d_in[17];
    const float* ln2b = (const float*)d_in[18];
    const float* Wh  = (const float*)d_in[19];
    const float* bh  = (const float*)d_in[20];
    float* out = (float*)d_out;

    float *x, *tb, *bqkv;
    __half *qkvh, *xh, *o16, *h16, *wbuf;
    cudaGetSymbolAddress((void**)&x,    g_x);
    cudaGetSymbolAddress((void**)&tb,   g_t);
    cudaGetSymbolAddress((void**)&bqkv, g_bqkv);
    cudaGetSymbolAddress((void**)&qkvh, g_qkvh);
    cudaGetSymbolAddress((void**)&xh,   g_xh);
    cudaGetSymbolAddress((void**)&o16,  g_o16);
    cudaGetSymbolAddress((void**)&h16,  g_h16);
    cudaGetSymbolAddress((void**)&wbuf, g_wbuf);

    cudaFuncSetAttribute(gemm16_kernel, cudaFuncAttributeMaxDynamicSharedMemorySize, GEMM_SMEM);

    long nQKV = (long)LL * HH * QKVW;
    int  nHH  = LL * HH * HH;
    int  nFF  = LL * HH * FF;

    const dim3 gQKV(QKVW / GN, MROWS / GM);
    const dim3 gHH (HH   / GN, MROWS / GM);
    const dim3 gFF (FF   / GN, MROWS / GM);
    const dim3 attnGrid(SS / CW, NHH, BB);
    const dim3 globGrid(GT, NHH, BB);

    // launches 0..3: embed, pack_qkv, pack_bqkv, gemmQKV  (ncu capture = index 3)
    {
        int total = MROWS * HH;
        embed_kernel<<<(total + 255) / 256, 256>>>(input_ids, emb, x, xh);
        pack_qkv_kernel<<<(int)((nQKV / 8 + 255) / 256), 256>>>(Wq, Wk, Wv, wbuf + WQKVOFF);
        pack_bqkv_kernel<<<(LL * QKVW + 255) / 256, 256>>>(bq, bk, bv, bqkv);
    }

    for (int l = 0; l < LL; l++) {
        const __half* wqkv = wbuf + WQKVOFF + (long)l * HH * QKVW;
        const __half* wo   = wbuf + WOOFF   + (long)l * HH * HH;
        const __half* w1   = wbuf + WF1OFF  + (long)l * HH * FF;
        const __half* w2   = wbuf + WF2OFF  + (long)l * FF * HH;

        gemm16_kernel<<<gQKV, 256, GEMM_SMEM>>>(xh, wqkv, bqkv + l * QKVW, nullptr, nullptr, qkvh, MROWS, QKVW, HH, 0);

        if (l == 0) {
            f2h_kernel<<<(nHH / 8 + 255) / 256, 256>>>(Wo,  wbuf + WOOFF,  nHH);
            f2h_kernel<<<(nFF / 8 + 255) / 256, 256>>>(Wf1, wbuf + WF1OFF, nFF);
            f2h_kernel<<<(nFF / 8 + 255) / 256, 256>>>(Wf2, wbuf + WF2OFF, nFF);
        }

        band_attn_kernel<<<attnGrid, 256>>>(qkvh, o16);
        glob_attn_kernel<<<globGrid, 128>>>(qkvh, o16);

        gemm16_kernel<<<gHH, 256, GEMM_SMEM>>>(o16, wo, bo + l * HH, x, tb, nullptr, MROWS, HH, HH, 1);
        ln_kernel<<<MROWS, 256>>>(tb, ln1g + l * HH, ln1b + l * HH, x, xh);

        gemm16_kernel<<<gFF, 256, GEMM_SMEM>>>(xh, w1, bf1 + l * FF, nullptr, nullptr, h16, MROWS, FF, HH, 2);
        gemm16_kernel<<<gHH, 256, GEMM_SMEM>>>(h16, w2, bf2 + l * HH, x, tb, nullptr, MROWS, HH, FF, 1);
        ln_kernel<<<MROWS, 256>>>(tb, ln2g + l * HH, ln2b + l * HH, x, xh);
    }

    head_kernel<<<BB * PP, 128>>>(x, pair_indices, Wh, bh, out);
}

// round 14
// speedup vs baseline: 1.0446x; 1.0446x over previous
#include <cuda_runtime.h>
#include <cuda_fp16.h>
#include <math.h>
#include <stdint.h>

// ---------------- problem constants ----------------
#define BB 2
#define SS 2048
#define HH 768
#define NHH 12
#define DD 64
#define LL 4
#define CW 128
#define GT 16
#define PP 128
#define NLC 3
#define FF (4*HH)
#define MROWS (BB*SS)
#define QKVW (3*HH)   // 2304

// ---------------- scratch ----------------
__device__ float  g_x   [MROWS*HH];
__device__ float  g_t   [MROWS*HH];
__device__ __half g_qkvh[MROWS*QKVW];
__device__ __half g_xh  [MROWS*HH];
__device__ __half g_o16 [MROWS*HH];
__device__ __half g_h16 [MROWS*FF];
__device__ float  g_bqkv[LL*QKVW];
#define WQKVOFF 0
#define WOOFF   (3*LL*HH*HH)
#define WF1OFF  (4*LL*HH*HH)
#define WF2OFF  (4*LL*HH*HH + LL*HH*FF)
#define WTOTAL  (4*LL*HH*HH + 2*LL*HH*FF)
__device__ __half g_wbuf[WTOTAL];

// ---------------- fp32 -> fp16 bulk convert ----------------
__global__ void f2h_kernel(const float* __restrict__ s, __half* __restrict__ d, int n)
{
    int i = (blockIdx.x * 256 + threadIdx.x) * 8;
    if (i >= n) return;
    float4 v0 = *(const float4*)&s[i];
    float4 v1 = *(const float4*)&s[i + 4];
    __half2 h0 = __floats2half2_rn(v0.x, v0.y);
    __half2 h1 = __floats2half2_rn(v0.z, v0.w);
    __half2 h2 = __floats2half2_rn(v1.x, v1.y);
    __half2 h3 = __floats2half2_rn(v1.z, v1.w);
    uint4 o;
    o.x = *reinterpret_cast<unsigned*>(&h0);
    o.y = *reinterpret_cast<unsigned*>(&h1);
    o.z = *reinterpret_cast<unsigned*>(&h2);
    o.w = *reinterpret_cast<unsigned*>(&h3);
    *(uint4*)&d[i] = o;
}

// ---------------- pack Wq|Wk|Wv -> [L][H][2304] fp16, scale q by 0.125 ----------------
__global__ void pack_qkv_kernel(const float* __restrict__ Wq, const float* __restrict__ Wk,
                                const float* __restrict__ Wv, __half* __restrict__ dst)
{
    long i = ((long)blockIdx.x * 256 + threadIdx.x) * 8;
    if (i >= (long)LL * HH * QKVW) return;
    int l   = (int)(i / (HH * QKVW));
    int rem = (int)(i - (long)l * HH * QKVW);
    int k   = rem / QKVW;
    int j   = rem - k * QKVW;
    int seg = j / HH;
    int jj  = j - seg * HH;
    const float* src = (seg == 0 ? Wq : seg == 1 ? Wk : Wv) + ((long)l * HH + k) * HH + jj;
    float sc = (seg == 0) ? 0.125f : 1.0f;
    float4 v0 = *(const float4*)&src[0];
    float4 v1 = *(const float4*)&src[4];
    __half2 h0 = __floats2half2_rn(v0.x * sc, v0.y * sc);
    __half2 h1 = __floats2half2_rn(v0.z * sc, v0.w * sc);
    __half2 h2 = __floats2half2_rn(v1.x * sc, v1.y * sc);
    __half2 h3 = __floats2half2_rn(v1.z * sc, v1.w * sc);
    uint4 o;
    o.x = *reinterpret_cast<unsigned*>(&h0);
    o.y = *reinterpret_cast<unsigned*>(&h1);
    o.z = *reinterpret_cast<unsigned*>(&h2);
    o.w = *reinterpret_cast<unsigned*>(&h3);
    *(uint4*)&dst[i] = o;
}

__global__ void pack_bqkv_kernel(const float* __restrict__ bq, const float* __restrict__ bk,
                                 const float* __restrict__ bv, float* __restrict__ dst)
{
    int i = blockIdx.x * 256 + threadIdx.x;
    if (i >= LL * QKVW) return;
    int l = i / QKVW;
    int j = i - l * QKVW;
    int seg = j / HH;
    int jj  = j - seg * HH;
    dst[i] = (seg == 0 ? bq[l * HH + jj] * 0.125f : seg == 1 ? bk[l * HH + jj] : bv[l * HH + jj]);
}

// ---------------- embedding gather ----------------
__global__ void embed_kernel(const int* __restrict__ ids,
                             const float* __restrict__ emb,
                             float* __restrict__ x, __half* __restrict__ xh)
{
    int idx = blockIdx.x * blockDim.x + threadIdx.x;
    if (idx >= MROWS * HH) return;
    int tok = idx / HH;
    int d   = idx - tok * HH;
    float e = emb[(long)ids[tok] * HH + d];
    x[idx]  = e;
    xh[idx] = __float2half(e);
}

// ---------------- fp16 tensor-core GEMM, CTA 128x128, 256 thr, 4-stage cp.async (R12 config) ----------------
// mode 0: Ch = AW+b (fp16); mode 1: Cf = AW+b+R; mode 2: Ch = gelu(AW+b)
#define GM 128
#define GN 128
#define NST 4

__device__ __forceinline__ void mma_f16(float* d, const unsigned* a, const unsigned* b) {
    asm volatile(
        "mma.sync.aligned.m16n8k16.row.col.f32.f16.f16.f32 "
        "{%0,%1,%2,%3}, {%4,%5,%6,%7}, {%8,%9}, {%0,%1,%2,%3};\n"
        : "+f"(d[0]), "+f"(d[1]), "+f"(d[2]), "+f"(d[3])
        : "r"(a[0]), "r"(a[1]), "r"(a[2]), "r"(a[3]),
          "r"(b[0]), "r"(b[1]));
}

__device__ __forceinline__ void cp16(unsigned smem, const void* g) {
    asm volatile("cp.async.cg.shared.global [%0], [%1], 16;\n" :: "r"(smem), "l"(g));
}

__global__ void __launch_bounds__(256, 2)
gemm16_kernel(const __half* __restrict__ A, const __half* __restrict__ W,
              const float* __restrict__ bias, const float* __restrict__ R,
              float* __restrict__ Cf, __half* __restrict__ Ch,
              int M, int N, int K, int mode)
{
    __shared__ unsigned As[NST][GM][12];
    __shared__ __half Bs[NST][16][GN];

    const int tid  = threadIdx.x;
    const int w    = tid >> 5;
    const int lane = tid & 31;
    const int gid  = lane >> 2;
    const int tig  = lane & 3;
    const int wm   = (w >> 1) * 32;
    const int wn   = (w & 1) * 64;
    const int row0 = blockIdx.y * GM;
    const int col0 = blockIdx.x * GN;

    const int ar = tid >> 1;
    const int ac = tid & 1;
    const int bk = tid >> 4;
    const int bc = tid & 15;
    const int bcs = bc ^ (bk & 7);

    const unsigned as_base = (unsigned)__cvta_generic_to_shared(&As[0][0][0]);
    const unsigned bs_base = (unsigned)__cvta_generic_to_shared(&Bs[0][0][0]);
    const unsigned a_dst0 = as_base + (ar * 12 + ac * 4) * 4;
    const unsigned b_dst0 = bs_base + bk * 256 + bcs * 16;

    const long arow_base = (long)(row0 + ar) * K + ac * 8;
    const long brow_col  = (long)col0 + bc * 8;

    const int lsel = lane >> 3;
    const int lk   = (lsel & 1) * 8 + (lane & 7);
    const int lnc  = (lsel >> 1);

    float acc[2][8][4];
#pragma unroll
    for (int mt = 0; mt < 2; mt++)
#pragma unroll
        for (int nt = 0; nt < 8; nt++)
#pragma unroll
            for (int u = 0; u < 4; u++) acc[mt][nt][u] = 0.f;

    const int nk = K / 16;

    auto load_stage = [&](int kt) {
        const int s = kt & 3;
        cp16(a_dst0 + s * 6144, &A[arow_base + kt * 16]);
        cp16(b_dst0 + s * 4096, &W[(long)(kt * 16 + bk) * N + brow_col]);
        asm volatile("cp.async.commit_group;\n");
    };

    load_stage(0);
    if (nk > 1) load_stage(1); else asm volatile("cp.async.commit_group;\n");
    if (nk > 2) load_stage(2); else asm volatile("cp.async.commit_group;\n");

    for (int kt = 0; kt < nk; kt++) {
        const int s = kt & 3;
        asm volatile("cp.async.wait_group 1;\n" ::: "memory");
        __syncthreads();

        if (kt + 3 < nk) load_stage(kt + 3);
        else asm volatile("cp.async.commit_group;\n");

        unsigned afr[2][4];
#pragma unroll
        for (int mt = 0; mt < 2; mt++) {
            int m = wm + mt * 16 + gid;
            afr[mt][0] = As[s][m    ][tig];
            afr[mt][1] = As[s][m + 8][tig];
            afr[mt][2] = As[s][m    ][tig + 4];
            afr[mt][3] = As[s][m + 8][tig + 4];
        }
        unsigned bfr[8][2];
#pragma unroll
        for (int ntp = 0; ntp < 4; ntp++) {
            int ncg = (wn >> 3) + ntp * 2 + lnc;
            int chunk = ncg ^ (lk & 7);
            unsigned addr = bs_base + s * 4096 + lk * 256 + chunk * 16;
            unsigned r0, r1, r2, r3;
            asm volatile(
                "ldmatrix.sync.aligned.m8n8.x4.trans.shared.b16 {%0,%1,%2,%3}, [%4];"
                : "=r"(r0), "=r"(r1), "=r"(r2), "=r"(r3) : "r"(addr));
            bfr[ntp * 2    ][0] = r0;
            bfr[ntp * 2    ][1] = r1;
            bfr[ntp * 2 + 1][0] = r2;
            bfr[ntp * 2 + 1][1] = r3;
        }
#pragma unroll
        for (int mt = 0; mt < 2; mt++)
#pragma unroll
            for (int nt = 0; nt < 8; nt++)
                mma_f16(acc[mt][nt], afr[mt], bfr[nt]);
    }

    // ---- epilogue ----
#pragma unroll
    for (int nt = 0; nt < 8; nt++) {
        const int cc = col0 + wn + nt * 8 + 2 * tig;
        float2 bv = *(const float2*)&bias[cc];
#pragma unroll
        for (int mt = 0; mt < 2; mt++) {
            int r0 = row0 + wm + mt * 16 + gid;
#pragma unroll
            for (int half_ = 0; half_ < 2; half_++) {
                int rr = r0 + half_ * 8;
                float vx = acc[mt][nt][half_ * 2 + 0] + bv.x;
                float vy = acc[mt][nt][half_ * 2 + 1] + bv.y;
                if (mode == 0) {
                    *(__half2*)&Ch[(long)rr * N + cc] = __floats2half2_rn(vx, vy);
                } else if (mode == 1) {
                    float2 rrv = *(const float2*)&R[(long)rr * N + cc];
                    *(float2*)&Cf[(long)rr * N + cc] = make_float2(vx + rrv.x, vy + rrv.y);
                } else {
                    float t0 = vx, t1 = vy;
                    vx = 0.5f * t0 * (1.f + tanhf(0.7978845608028654f * (t0 + 0.044715f * t0 * t0 * t0)));
                    vy = 0.5f * t1 * (1.f + tanhf(0.7978845608028654f * (t1 + 0.044715f * t1 * t1 * t1)));
                    *(__half2*)&Ch[(long)rr * N + cc] = __floats2half2_rn(vx, vy);
                }
            }
        }
    }
}

// ---------------- layernorm over H=768 ----------------
__global__ void __launch_bounds__(256)
ln_kernel(const float* __restrict__ in, const float* __restrict__ g,
          const float* __restrict__ b, float* __restrict__ out, __half* __restrict__ outh)
{
    const int row = blockIdx.x;
    const float* x = in + (long)row * HH;
    float v0[3];
    float s = 0.f, s2 = 0.f;
#pragma unroll
    for (int i = 0; i < 3; i++) {
        float t = x[threadIdx.x + i * 256];
        v0[i] = t; s += t; s2 += t * t;
    }
#pragma unroll
    for (int o = 16; o > 0; o >>= 1) {
        s  += __shfl_xor_sync(0xffffffffu, s, o);
        s2 += __shfl_xor_sync(0xffffffffu, s2, o);
    }
    __shared__ float red0[8], red1[8];
    int w = threadIdx.x >> 5;
    if ((threadIdx.x & 31) == 0) { red0[w] = s; red1[w] = s2; }
    __syncthreads();
    if (threadIdx.x < 32) {
        s  = (threadIdx.x < 8) ? red0[threadIdx.x] : 0.f;
        s2 = (threadIdx.x < 8) ? red1[threadIdx.x] : 0.f;
#pragma unroll
        for (int o = 4; o > 0; o >>= 1) {
            s  += __shfl_xor_sync(0xffffffffu, s, o);
            s2 += __shfl_xor_sync(0xffffffffu, s2, o);
        }
        if (threadIdx.x == 0) { red0[0] = s; red1[0] = s2; }
    }
    __syncthreads();
    float mean = red0[0] * (1.f / HH);
    float var  = red1[0] * (1.f / HH) - mean * mean;
    float rstd = rsqrtf(var + 1e-5f);
#pragma unroll
    for (int i = 0; i < 3; i++) {
        int c = threadIdx.x + i * 256;
        float val = (v0[i] - mean) * rstd * g[c] + b[c];
        out [(long)row * HH + c] = val;
        outh[(long)row * HH + c] = __float2half(val);
    }
}

// ---------------- banded attention via mma (fp16 qkv) ----------------
__global__ void __launch_bounds__(256)
band_attn_kernel(const __half* __restrict__ qkv, __half* __restrict__ o)
{
    const int n = blockIdx.x, h = blockIdx.y, b = blockIdx.z;
    const int tid  = threadIdx.x;
    const int w    = tid >> 5;
    const int lane = tid & 31;
    const int gid  = lane >> 2;
    const int tig  = lane & 3;

    __shared__ __align__(16) char smem[2][2][64 * 128];
    const unsigned smem_base = (unsigned)__cvta_generic_to_shared(&smem[0][0][0]);

    const int s_q0 = n * CW + w * 16 + gid;
    const int s_q1 = s_q0 + 8;

    unsigned qf[4][4];
    {
        const __half* q0 = qkv + ((long)(b * SS + s_q0) * QKVW + h * DD);
        const __half* q1 = qkv + ((long)(b * SS + s_q1) * QKVW + h * DD);
#pragma unroll
        for (int kk = 0; kk < 4; kk++) {
            int d0 = kk * 16 + 2 * tig;
            qf[kk][0] = *(const unsigned*)(q0 + d0);
            qf[kk][1] = *(const unsigned*)(q1 + d0);
            qf[kk][2] = *(const unsigned*)(q0 + d0 + 8);
            qf[kk][3] = *(const unsigned*)(q1 + d0 + 8);
        }
    }

    float m0 = -1e30f, m1 = -1e30f, l0 = 0.f, l1 = 0.f;
    float accO[8][4];
#pragma unroll
    for (int dt = 0; dt < 8; dt++)
#pragma unroll
        for (int u = 0; u < 4; u++) accO[dt][u] = 0.f;

    auto fill = [&](int t) {
        const int buf = t & 1;
#pragma unroll
        for (int i = 0; i < 4; i++) {
            int g = tid + i * 256;
            int tensor = g >> 9;
            int within = g & 511;
            int row = within >> 3;
            int c   = within & 7;
            int p  = (t == 6) ? row : (n * CW - CW + t * 64 + row);
            int pc = min(max(p, 0), SS - 1);
            const __half* src = qkv + ((long)(b * SS + pc) * QKVW + (tensor ? 2 * HH : HH) + h * DD + c * 8);
            unsigned dst = smem_base + buf * 16384 + tensor * 8192 + row * 128 + (((unsigned)(c ^ (row & 7))) << 4);
            cp16(dst, src);
        }
        asm volatile("cp.async.commit_group;\n");
    };

    fill(0);

    for (int t = 0; t < 7; t++) {
        const int buf = t & 1;
        if (t + 1 < 7) {
            fill(t + 1);
            asm volatile("cp.async.wait_group 1;\n" ::: "memory");
        } else {
            asm volatile("cp.async.wait_group 0;\n" ::: "memory");
        }
        __syncthreads();

        const unsigned kb = smem_base + buf * 16384;
        const unsigned vb = kb + 8192;

        float s[8][4];
#pragma unroll
        for (int ng = 0; ng < 8; ng++)
#pragma unroll
            for (int u = 0; u < 4; u++) s[ng][u] = 0.f;

#pragma unroll
        for (int ng = 0; ng < 8; ng++) {
#pragma unroll
            for (int kp = 0; kp < 2; kp++) {
                int row = ng * 8 + (lane & 7);
                int ci  = kp * 4 + (lane >> 3);
                unsigned addr = kb + row * 128 + (((unsigned)(ci ^ (row & 7))) << 4);
                unsigned r0, r1, r2, r3;
                asm volatile(
                    "ldmatrix.sync.aligned.m8n8.x4.shared.b16 {%0,%1,%2,%3}, [%4];"
                    : "=r"(r0), "=r"(r1), "=r"(r2), "=r"(r3) : "r"(addr));
                unsigned bf0[2] = {r0, r1};
                unsigned bf1[2] = {r2, r3};
                mma_f16(s[ng], qf[kp * 2],     bf0);
                mma_f16(s[ng], qf[kp * 2 + 1], bf1);
            }
        }

        const int p00 = (t == 6) ? 0 : (n * CW - CW + t * 64);
#pragma unroll
        for (int ng = 0; ng < 8; ng++) {
            int k0 = ng * 8 + 2 * tig;
            int p0v = p00 + k0;
            int p1v = p0v + 1;
            bool v00, v01, v10, v11;
            if (t == 6) {
                v00 = v10 = (k0 < GT);
                v01 = v11 = (k0 + 1 < GT);
            } else {
                bool base0 = (p0v >= GT) && (p0v < SS);
                bool base1 = (p1v >= GT) && (p1v < SS);
                v00 = base0 && (abs(p0v - s_q0) <= CW);
                v10 = base0 && (abs(p0v - s_q1) <= CW);
                v01 = base1 && (abs(p1v - s_q0) <= CW);
                v11 = base1 && (abs(p1v - s_q1) <= CW);
            }
            if (!v00) s[ng][0] = -1e30f;
            if (!v01) s[ng][1] = -1e30f;
            if (!v10) s[ng][2] = -1e30f;
            if (!v11) s[ng][3] = -1e30f;
        }

        float t0 = -1e30f, t1 = -1e30f;
#pragma unroll
        for (int ng = 0; ng < 8; ng++) {
            t0 = fmaxf(t0, fmaxf(s[ng][0], s[ng][1]));
            t1 = fmaxf(t1, fmaxf(s[ng][2], s[ng][3]));
        }
        t0 = fmaxf(t0, __shfl_xor_sync(0xffffffffu, t0, 1));
        t0 = fmaxf(t0, __shfl_xor_sync(0xffffffffu, t0, 2));
        t1 = fmaxf(t1, __shfl_xor_sync(0xffffffffu, t1, 1));
        t1 = fmaxf(t1, __shfl_xor_sync(0xffffffffu, t1, 2));

        float mn0 = fmaxf(m0, t0), mn1 = fmaxf(m1, t1);
        float al0 = __expf(m0 - mn0), al1 = __expf(m1 - mn1);
        l0 *= al0; l1 *= al1;
#pragma unroll
        for (int dt = 0; dt < 8; dt++) {
            accO[dt][0] *= al0; accO[dt][1] *= al0;
            accO[dt][2] *= al1; accO[dt][3] *= al1;
        }

        unsigned ph[8][2];
#pragma unroll
        for (int ng = 0; ng < 8; ng++) {
            float p0 = (s[ng][0] < -1e29f) ? 0.f : __expf(s[ng][0] - mn0);
            float p1 = (s[ng][1] < -1e29f) ? 0.f : __expf(s[ng][1] - mn0);
            float p2 = (s[ng][2] < -1e29f) ? 0.f : __expf(s[ng][2] - mn1);
            float p3 = (s[ng][3] < -1e29f) ? 0.f : __expf(s[ng][3] - mn1);
            l0 += p0 + p1;
            l1 += p2 + p3;
            __half2 h01 = __floats2half2_rn(p0, p1);
            __half2 h23 = __floats2half2_rn(p2, p3);
            ph[ng][0] = *reinterpret_cast<unsigned*>(&h01);
            ph[ng][1] = *reinterpret_cast<unsigned*>(&h23);
        }
        m0 = mn0; m1 = mn1;

        const int lsel = lane >> 3;
        const int lk   = (lsel & 1) * 8 + (lane & 7);
        const int lnc  = lsel >> 1;
#pragma unroll
        for (int kk = 0; kk < 4; kk++) {
            unsigned af[4] = { ph[2 * kk][0], ph[2 * kk][1], ph[2 * kk + 1][0], ph[2 * kk + 1][1] };
#pragma unroll
            for (int dp = 0; dp < 4; dp++) {
                int row = kk * 16 + lk;
                int ci  = (dp * 2 + lnc) ^ (row & 7);
                unsigned addr = vb + row * 128 + (((unsigned)ci) << 4);
                unsigned r0, r1, r2, r3;
                asm volatile(
                    "ldmatrix.sync.aligned.m8n8.x4.trans.shared.b16 {%0,%1,%2,%3}, [%4];"
                    : "=r"(r0), "=r"(r1), "=r"(r2), "=r"(r3) : "r"(addr));
                unsigned b0[2] = {r0, r1};
                unsigned b1[2] = {r2, r3};
                mma_f16(accO[dp * 2],     af, b0);
                mma_f16(accO[dp * 2 + 1], af, b1);
            }
        }
        __syncthreads();
    }

    l0 += __shfl_xor_sync(0xffffffffu, l0, 1);
    l0 += __shfl_xor_sync(0xffffffffu, l0, 2);
    l1 += __shfl_xor_sync(0xffffffffu, l1, 1);
    l1 += __shfl_xor_sync(0xffffffffu, l1, 2);
    float i0 = 1.f / l0, i1 = 1.f / l1;

    __half* o0 = o + ((long)(b * SS + s_q0) * HH + h * DD);
    __half* o1 = o + ((long)(b * SS + s_q1) * HH + h * DD);
#pragma unroll
    for (int dt = 0; dt < 8; dt++) {
        int d0 = dt * 8 + 2 * tig;
        *(__half2*)(o0 + d0) = __floats2half2_rn(accO[dt][0] * i0, accO[dt][1] * i0);
        *(__half2*)(o1 + d0) = __floats2half2_rn(accO[dt][2] * i1, accO[dt][3] * i1);
    }
}

// ---------------- global-query attention (fp16 qkv) ----------------
__global__ void __launch_bounds__(128)
glob_attn_kernel(const __half* __restrict__ qkv, __half* __restrict__ o)
{
    const int g = blockIdx.x, h = blockIdx.y, b = blockIdx.z;
    const int tid = threadIdx.x;

    __shared__ float qs[DD];
    __shared__ float sc[SS];
    __shared__ float red[4];
    __shared__ float part[4][DD];

    if (tid < DD) qs[tid] = __half2float(qkv[(long)(b * SS + g) * QKVW + h * DD + tid]);
    __syncthreads();

    float lm = -1e30f;
    for (int s = tid; s < SS; s += 128) {
        const __half* kr = qkv + ((long)(b * SS + s) * QKVW + HH + h * DD);
        float acc = 0.f;
#pragma unroll
        for (int c = 0; c < 8; c++) {
            uint4 raw = *(const uint4*)(kr + c * 8);
            __half2* hp = (__half2*)&raw;
#pragma unroll
            for (int u = 0; u < 4; u++) {
                float2 kf = __half22float2(hp[u]);
                acc += qs[c * 8 + 2 * u] * kf.x + qs[c * 8 + 2 * u + 1] * kf.y;
            }
        }
        sc[s] = acc;
        lm = fmaxf(lm, acc);
    }
#pragma unroll
    for (int off = 16; off > 0; off >>= 1)
        lm = fmaxf(lm, __shfl_xor_sync(0xffffffffu, lm, off));
    if ((tid & 31) == 0) red[tid >> 5] = lm;
    __syncthreads();
    float m = fmaxf(fmaxf(red[0], red[1]), fmaxf(red[2], red[3]));

    float ls = 0.f;
    for (int s = tid; s < SS; s += 128) {
        float e = __expf(sc[s] - m);
        sc[s] = e;
        ls += e;
    }
#pragma unroll
    for (int off = 16; off > 0; off >>= 1)
        ls += __shfl_xor_sync(0xffffffffu, ls, off);
    __syncthreads();
    if ((tid & 31) == 0) red[tid >> 5] = ls;
    __syncthreads();
    float l = red[0] + red[1] + red[2] + red[3];

    const int d2  = (tid & 31) * 2;
    const int grp = tid >> 5;
    float2 acc2 = make_float2(0.f, 0.f);
    const __half* vp = qkv + ((long)(b * SS) * QKVW + 2 * HH + h * DD + d2);
    const int s0 = grp * (SS / 4);
    for (int s = s0; s < s0 + SS / 4; s++) {
        __half2 hv = *(const __half2*)(vp + (long)s * QKVW);
        float2 f = __half22float2(hv);
        acc2.x += sc[s] * f.x;
        acc2.y += sc[s] * f.y;
    }
    part[grp][d2]     = acc2.x;
    part[grp][d2 + 1] = acc2.y;
    __syncthreads();
    if (tid < DD) {
        float inv = 1.f / l;
        float v = (part[0][tid] + part[1][tid] + part[2][tid] + part[3][tid]) * inv;
        o[(long)(b * SS + g) * HH + h * DD + tid] = __float2half(v);
    }
}

// ---------------- pair gather + classifier head ----------------
__global__ void __launch_bounds__(128)
head_kernel(const float* __restrict__ x, const int* __restrict__ pairs,
            const float* __restrict__ Wh, const float* __restrict__ bh,
            float* __restrict__ out)
{
    const int bp = blockIdx.x;
    const int b = bp >> 7;
    const int i = pairs[bp * 2 + 0];
    const int j = pairs[bp * 2 + 1];
    const float* xi = x + (long)(b * SS + i) * HH;
    const float* xj = x + (long)(b * SS + j) * HH;

    float acc[NLC] = {0.f, 0.f, 0.f};
    for (int d = threadIdx.x; d < 2 * HH; d += 128) {
        float e = (d < HH) ? xi[d] : xj[d - HH];
        acc[0] += e * Wh[d * NLC + 0];
        acc[1] += e * Wh[d * NLC + 1];
        acc[2] += e * Wh[d * NLC + 2];
    }
#pragma unroll
    for (int o = 16; o > 0; o >>= 1) {
#pragma unroll
        for (int c = 0; c < NLC; c++)
            acc[c] += __shfl_xor_sync(0xffffffffu, acc[c], o);
    }
    __shared__ float sm[NLC][4];
    int w = threadIdx.x >> 5;
    if ((threadIdx.x & 31) == 0) {
#pragma unroll
        for (int c = 0; c < NLC; c++) sm[c][w] = acc[c];
    }
    __syncthreads();
    if (threadIdx.x < NLC) {
        float s = sm[threadIdx.x][0] + sm[threadIdx.x][1] + sm[threadIdx.x][2] + sm[threadIdx.x][3];
        out[bp * NLC + threadIdx.x] = s + bh[threadIdx.x];
    }
}

// ---------------- host orchestration ----------------
extern "C" void kernel_launch(void* const* d_in, const int* in_sizes, int n_in,
                              void* d_out, int out_size)
{
    const int*   input_ids    = (const int*)  d_in[0];
    const int*   pair_indices = (const int*)  d_in[1];
    const float* emb          = (const float*)d_in[2];
    const float* Wq  = (const float*)d_in[3];
    const float* bq  = (const float*)d_in[4];
    const float* Wk  = (const float*)d_in[5];
    const float* bk  = (const float*)d_in[6];
    const float* Wv  = (const float*)d_in[7];
    const float* bv  = (const float*)d_in[8];
    const float* Wo  = (const float*)d_in[9];
    const float* bo  = (const float*)d_in[10];
    const float* ln1g = (const float*)d_in[11];
    const float* ln1b = (const float*)d_in[12];
    const float* Wf1 = (const float*)d_in[13];
    const float* bf1 = (const float*)d_in[14];
    const float* Wf2 = (const float*)d_in[15];
    const float* bf2 = (const float*)d_in[16];
    const float* ln2g = (const float*)d_in[17];
    const float* ln2b = (const float*)d_in[18];
    const float* Wh  = (const float*)d_in[19];
    const float* bh  = (const float*)d_in[20];
    float* out = (float*)d_out;

    float *x, *tb, *bqkv;
    __half *qkvh, *xh, *o16, *h16, *wbuf;
    cudaGetSymbolAddress((void**)&x,    g_x);
    cudaGetSymbolAddress((void**)&tb,   g_t);
    cudaGetSymbolAddress((void**)&bqkv, g_bqkv);
    cudaGetSymbolAddress((void**)&qkvh, g_qkvh);
    cudaGetSymbolAddress((void**)&xh,   g_xh);
    cudaGetSymbolAddress((void**)&o16,  g_o16);
    cudaGetSymbolAddress((void**)&h16,  g_h16);
    cudaGetSymbolAddress((void**)&wbuf, g_wbuf);

    long nQKV = (long)LL * HH * QKVW;
    int  nHH  = LL * HH * HH;
    int  nFF  = LL * HH * FF;

    const dim3 gQKV(QKVW / GN, MROWS / GM);
    const dim3 gHH (HH   / GN, MROWS / GM);
    const dim3 gFF (FF   / GN, MROWS / GM);
    const dim3 attnGrid(SS / CW, NHH, BB);
    const dim3 globGrid(GT, NHH, BB);

    // launches 0..3: embed, pack_qkv, pack_bqkv, gemmQKV  (ncu capture = index 3)
    {
        int total = MROWS * HH;
        embed_kernel<<<(total + 255) / 256, 256>>>(input_ids, emb, x, xh);
        pack_qkv_kernel<<<(int)((nQKV / 8 + 255) / 256), 256>>>(Wq, Wk, Wv, wbuf + WQKVOFF);
        pack_bqkv_kernel<<<(LL * QKVW + 255) / 256, 256>>>(bq, bk, bv, bqkv);
    }

    for (int l = 0; l < LL; l++) {
        const __half* wqkv = wbuf + WQKVOFF + (long)l * HH * QKVW;
        const __half* wo   = wbuf + WOOFF   + (long)l * HH * HH;
        const __half* w1   = wbuf + WF1OFF  + (long)l * HH * FF;
        const __half* w2   = wbuf + WF2OFF  + (long)l * FF * HH;

        gemm16_kernel<<<gQKV, 256>>>(xh, wqkv, bqkv + l * QKVW, nullptr, nullptr, qkvh, MROWS, QKVW, HH, 0);

        if (l == 0) {
            f2h_kernel<<<(nHH / 8 + 255) / 256, 256>>>(Wo,  wbuf + WOOFF,  nHH);
            f2h_kernel<<<(nFF / 8 + 255) / 256, 256>>>(Wf1, wbuf + WF1OFF, nFF);
            f2h_kernel<<<(nFF / 8 + 255) / 256, 256>>>(Wf2, wbuf + WF2OFF, nFF);
        }

        band_attn_kernel<<<attnGrid, 256>>>(qkvh, o16);
        glob_attn_kernel<<<globGrid, 128>>>(qkvh, o16);

        gemm16_kernel<<<gHH, 256>>>(o16, wo, bo + l * HH, x, tb, nullptr, MROWS, HH, HH, 1);
        ln_kernel<<<MROWS, 256>>>(tb, ln1g + l * HH, ln1b + l * HH, x, xh);

        gemm16_kernel<<<gFF, 256>>>(xh, w1, bf1 + l * FF, nullptr, nullptr, h16, MROWS, FF, HH, 2);
        gemm16_kernel<<<gHH, 256>>>(h16, w2, bf2 + l * HH, x, tb, nullptr, MROWS, HH, FF, 1);
        ln_kernel<<<MROWS, 256>>>(tb, ln2g + l * HH, ln2b + l * HH, x, xh);
    }

    head_kernel<<<BB * PP, 128>>>(x, pair_indices, Wh, bh, out);
}

// round 15
// speedup vs baseline: 1.0904x; 1.0439x over previous
#include <cuda_runtime.h>
#include <cuda_fp16.h>
#include <math.h>
#include <stdint.h>

// ---------------- problem constants ----------------
#define BB 2
#define SS 2048
#define HH 768
#define NHH 12
#define DD 64
#define LL 4
#define CW 128
#define GT 16
#define PP 128
#define NLC 3
#define FF (4*HH)
#define MROWS (BB*SS)
#define QKVW (3*HH)   // 2304

// ---------------- scratch ----------------
__device__ float  g_x   [MROWS*HH];
__device__ float  g_t   [MROWS*HH];
__device__ __half g_qkvh[MROWS*QKVW];
__device__ __half g_xh  [MROWS*HH];
__device__ __half g_o16 [MROWS*HH];
__device__ __half g_h16 [MROWS*FF];
__device__ float  g_bqkv[LL*QKVW];
#define WQKVOFF 0
#define WOOFF   (3*LL*HH*HH)
#define WF1OFF  (4*LL*HH*HH)
#define WF2OFF  (4*LL*HH*HH + LL*HH*FF)
#define WTOTAL  (4*LL*HH*HH + 2*LL*HH*FF)
__device__ __half g_wbuf[WTOTAL];

// ---------------- fp32 -> fp16 bulk convert ----------------
__global__ void f2h_kernel(const float* __restrict__ s, __half* __restrict__ d, int n)
{
    int i = (blockIdx.x * 256 + threadIdx.x) * 8;
    if (i >= n) return;
    float4 v0 = *(const float4*)&s[i];
    float4 v1 = *(const float4*)&s[i + 4];
    __half2 h0 = __floats2half2_rn(v0.x, v0.y);
    __half2 h1 = __floats2half2_rn(v0.z, v0.w);
    __half2 h2 = __floats2half2_rn(v1.x, v1.y);
    __half2 h3 = __floats2half2_rn(v1.z, v1.w);
    uint4 o;
    o.x = *reinterpret_cast<unsigned*>(&h0);
    o.y = *reinterpret_cast<unsigned*>(&h1);
    o.z = *reinterpret_cast<unsigned*>(&h2);
    o.w = *reinterpret_cast<unsigned*>(&h3);
    *(uint4*)&d[i] = o;
}

// ---------------- pack Wq|Wk|Wv -> [L][H][2304] fp16, scale q by 0.125 ----------------
__global__ void pack_qkv_kernel(const float* __restrict__ Wq, const float* __restrict__ Wk,
                                const float* __restrict__ Wv, __half* __restrict__ dst)
{
    long i = ((long)blockIdx.x * 256 + threadIdx.x) * 8;
    if (i >= (long)LL * HH * QKVW) return;
    int l   = (int)(i / (HH * QKVW));
    int rem = (int)(i - (long)l * HH * QKVW);
    int k   = rem / QKVW;
    int j   = rem - k * QKVW;
    int seg = j / HH;
    int jj  = j - seg * HH;
    const float* src = (seg == 0 ? Wq : seg == 1 ? Wk : Wv) + ((long)l * HH + k) * HH + jj;
    float sc = (seg == 0) ? 0.125f : 1.0f;
    float4 v0 = *(const float4*)&src[0];
    float4 v1 = *(const float4*)&src[4];
    __half2 h0 = __floats2half2_rn(v0.x * sc, v0.y * sc);
    __half2 h1 = __floats2half2_rn(v0.z * sc, v0.w * sc);
    __half2 h2 = __floats2half2_rn(v1.x * sc, v1.y * sc);
    __half2 h3 = __floats2half2_rn(v1.z * sc, v1.w * sc);
    uint4 o;
    o.x = *reinterpret_cast<unsigned*>(&h0);
    o.y = *reinterpret_cast<unsigned*>(&h1);
    o.z = *reinterpret_cast<unsigned*>(&h2);
    o.w = *reinterpret_cast<unsigned*>(&h3);
    *(uint4*)&dst[i] = o;
}

__global__ void pack_bqkv_kernel(const float* __restrict__ bq, const float* __restrict__ bk,
                                 const float* __restrict__ bv, float* __restrict__ dst)
{
    int i = blockIdx.x * 256 + threadIdx.x;
    if (i >= LL * QKVW) return;
    int l = i / QKVW;
    int j = i - l * QKVW;
    int seg = j / HH;
    int jj  = j - seg * HH;
    dst[i] = (seg == 0 ? bq[l * HH + jj] * 0.125f : seg == 1 ? bk[l * HH + jj] : bv[l * HH + jj]);
}

// ---------------- embedding gather ----------------
__global__ void embed_kernel(const int* __restrict__ ids,
                             const float* __restrict__ emb,
                             float* __restrict__ x, __half* __restrict__ xh)
{
    int idx = blockIdx.x * blockDim.x + threadIdx.x;
    if (idx >= MROWS * HH) return;
    int tok = idx / HH;
    int d   = idx - tok * HH;
    float e = emb[(long)ids[tok] * HH + d];
    x[idx]  = e;
    xh[idx] = __float2half(e);
}

// ---------------- shared mma helpers ----------------
__device__ __forceinline__ void mma_f16(float* d, const unsigned* a, const unsigned* b) {
    asm volatile(
        "mma.sync.aligned.m16n8k16.row.col.f32.f16.f16.f32 "
        "{%0,%1,%2,%3}, {%4,%5,%6,%7}, {%8,%9}, {%0,%1,%2,%3};\n"
        : "+f"(d[0]), "+f"(d[1]), "+f"(d[2]), "+f"(d[3])
        : "r"(a[0]), "r"(a[1]), "r"(a[2]), "r"(a[3]),
          "r"(b[0]), "r"(b[1]));
}

__device__ __forceinline__ void cp16(unsigned smem, const void* g) {
    asm volatile("cp.async.cg.shared.global [%0], [%1], 16;\n" :: "r"(smem), "l"(g));
}

// ---------------- fp16 GEMM, CTA 128x128, 256 thr (R12 config) ----------------
// mode 0: Ch = AW+b (fp16); mode 1: Cf = AW+b+R; mode 2: Ch = gelu(AW+b)
#define GM 128
#define GN 128
#define NST 4

__global__ void __launch_bounds__(256, 2)
gemm16_kernel(const __half* __restrict__ A, const __half* __restrict__ W,
              const float* __restrict__ bias, const float* __restrict__ R,
              float* __restrict__ Cf, __half* __restrict__ Ch,
              int M, int N, int K, int mode)
{
    __shared__ unsigned As[NST][GM][12];
    __shared__ __half Bs[NST][16][GN];

    const int tid  = threadIdx.x;
    const int w    = tid >> 5;
    const int lane = tid & 31;
    const int gid  = lane >> 2;
    const int tig  = lane & 3;
    const int wm   = (w >> 1) * 32;
    const int wn   = (w & 1) * 64;
    const int row0 = blockIdx.y * GM;
    const int col0 = blockIdx.x * GN;

    const int ar = tid >> 1;
    const int ac = tid & 1;
    const int bk = tid >> 4;
    const int bc = tid & 15;
    const int bcs = bc ^ (bk & 7);

    const unsigned as_base = (unsigned)__cvta_generic_to_shared(&As[0][0][0]);
    const unsigned bs_base = (unsigned)__cvta_generic_to_shared(&Bs[0][0][0]);
    const unsigned a_dst0 = as_base + (ar * 12 + ac * 4) * 4;
    const unsigned b_dst0 = bs_base + bk * 256 + bcs * 16;

    const long arow_base = (long)(row0 + ar) * K + ac * 8;
    const long brow_col  = (long)col0 + bc * 8;

    const int lsel = lane >> 3;
    const int lk   = (lsel & 1) * 8 + (lane & 7);
    const int lnc  = (lsel >> 1);

    float acc[2][8][4];
#pragma unroll
    for (int mt = 0; mt < 2; mt++)
#pragma unroll
        for (int nt = 0; nt < 8; nt++)
#pragma unroll
            for (int u = 0; u < 4; u++) acc[mt][nt][u] = 0.f;

    const int nk = K / 16;

    auto load_stage = [&](int kt) {
        const int s = kt & 3;
        cp16(a_dst0 + s * 6144, &A[arow_base + kt * 16]);
        cp16(b_dst0 + s * 4096, &W[(long)(kt * 16 + bk) * N + brow_col]);
        asm volatile("cp.async.commit_group;\n");
    };

    load_stage(0);
    if (nk > 1) load_stage(1); else asm volatile("cp.async.commit_group;\n");
    if (nk > 2) load_stage(2); else asm volatile("cp.async.commit_group;\n");

    for (int kt = 0; kt < nk; kt++) {
        const int s = kt & 3;
        asm volatile("cp.async.wait_group 1;\n" ::: "memory");
        __syncthreads();

        if (kt + 3 < nk) load_stage(kt + 3);
        else asm volatile("cp.async.commit_group;\n");

        unsigned afr[2][4];
#pragma unroll
        for (int mt = 0; mt < 2; mt++) {
            int m = wm + mt * 16 + gid;
            afr[mt][0] = As[s][m    ][tig];
            afr[mt][1] = As[s][m + 8][tig];
            afr[mt][2] = As[s][m    ][tig + 4];
            afr[mt][3] = As[s][m + 8][tig + 4];
        }
        unsigned bfr[8][2];
#pragma unroll
        for (int ntp = 0; ntp < 4; ntp++) {
            int ncg = (wn >> 3) + ntp * 2 + lnc;
            int chunk = ncg ^ (lk & 7);
            unsigned addr = bs_base + s * 4096 + lk * 256 + chunk * 16;
            unsigned r0, r1, r2, r3;
            asm volatile(
                "ldmatrix.sync.aligned.m8n8.x4.trans.shared.b16 {%0,%1,%2,%3}, [%4];"
                : "=r"(r0), "=r"(r1), "=r"(r2), "=r"(r3) : "r"(addr));
            bfr[ntp * 2    ][0] = r0;
            bfr[ntp * 2    ][1] = r1;
            bfr[ntp * 2 + 1][0] = r2;
            bfr[ntp * 2 + 1][1] = r3;
        }
#pragma unroll
        for (int mt = 0; mt < 2; mt++)
#pragma unroll
            for (int nt = 0; nt < 8; nt++)
                mma_f16(acc[mt][nt], afr[mt], bfr[nt]);
    }

#pragma unroll
    for (int nt = 0; nt < 8; nt++) {
        const int cc = col0 + wn + nt * 8 + 2 * tig;
        float2 bv = *(const float2*)&bias[cc];
#pragma unroll
        for (int mt = 0; mt < 2; mt++) {
            int r0 = row0 + wm + mt * 16 + gid;
#pragma unroll
            for (int half_ = 0; half_ < 2; half_++) {
                int rr = r0 + half_ * 8;
                float vx = acc[mt][nt][half_ * 2 + 0] + bv.x;
                float vy = acc[mt][nt][half_ * 2 + 1] + bv.y;
                if (mode == 0) {
                    *(__half2*)&Ch[(long)rr * N + cc] = __floats2half2_rn(vx, vy);
                } else if (mode == 1) {
                    float2 rrv = *(const float2*)&R[(long)rr * N + cc];
                    *(float2*)&Cf[(long)rr * N + cc] = make_float2(vx + rrv.x, vy + rrv.y);
                } else {
                    float t0 = vx, t1 = vy;
                    vx = 0.5f * t0 * (1.f + tanhf(0.7978845608028654f * (t0 + 0.044715f * t0 * t0 * t0)));
                    vy = 0.5f * t1 * (1.f + tanhf(0.7978845608028654f * (t1 + 0.044715f * t1 * t1 * t1)));
                    *(__half2*)&Ch[(long)rr * N + cc] = __floats2half2_rn(vx, vy);
                }
            }
        }
    }
}

// ---------------- fp16 GEMM variant: CTA 64x128, 128 thr, 4 warps ----------------
// Used for N=768 GEMMs (Wo, Wf2): 384-CTA grids fix the 192-CTA tail imbalance.
__global__ void __launch_bounds__(128, 4)
gemm16s_kernel(const __half* __restrict__ A, const __half* __restrict__ W,
               const float* __restrict__ bias, const float* __restrict__ R,
               float* __restrict__ Cf, __half* __restrict__ Ch,
               int M, int N, int K, int mode)
{
    __shared__ unsigned As[NST][64][12];   // 12 KB
    __shared__ __half Bs[NST][16][GN];     // 16 KB

    const int tid  = threadIdx.x;
    const int w    = tid >> 5;
    const int lane = tid & 31;
    const int gid  = lane >> 2;
    const int tig  = lane & 3;
    const int wm   = (w >> 1) * 32;        // 0 or 32
    const int wn   = (w & 1) * 64;
    const int row0 = blockIdx.y * 64;
    const int col0 = blockIdx.x * GN;

    // A staging: 64 rows x 2 chunks = 128 cp16 (1/thread)
    const int ar = tid >> 1;
    const int ac = tid & 1;
    // B staging: 16 rows x 16 chunks = 256 cp16 (2/thread: rows bk, bk+8)
    const int bk = tid >> 4;               // 0..7
    const int bc = tid & 15;
    const int bcs = bc ^ (bk & 7);         // same swizzle for row bk+8 ((bk+8)&7 == bk&7)

    const unsigned as_base = (unsigned)__cvta_generic_to_shared(&As[0][0][0]);
    const unsigned bs_base = (unsigned)__cvta_generic_to_shared(&Bs[0][0][0]);
    const unsigned a_dst0 = as_base + (ar * 12 + ac * 4) * 4;
    const unsigned b_dst0 = bs_base + bk * 256 + bcs * 16;

    const long arow_base = (long)(row0 + ar) * K + ac * 8;
    const long brow_col  = (long)col0 + bc * 8;

    const int lsel = lane >> 3;
    const int lk   = (lsel & 1) * 8 + (lane & 7);
    const int lnc  = (lsel >> 1);

    float acc[2][8][4];
#pragma unroll
    for (int mt = 0; mt < 2; mt++)
#pragma unroll
        for (int nt = 0; nt < 8; nt++)
#pragma unroll
            for (int u = 0; u < 4; u++) acc[mt][nt][u] = 0.f;

    const int nk = K / 16;

    auto load_stage = [&](int kt) {
        const int s = kt & 3;
        cp16(a_dst0 + s * 3072, &A[arow_base + kt * 16]);
        cp16(b_dst0 + s * 4096,        &W[(long)(kt * 16 + bk)     * N + brow_col]);
        cp16(b_dst0 + s * 4096 + 2048, &W[(long)(kt * 16 + bk + 8) * N + brow_col]);
        asm volatile("cp.async.commit_group;\n");
    };

    load_stage(0);
    if (nk > 1) load_stage(1); else asm volatile("cp.async.commit_group;\n");
    if (nk > 2) load_stage(2); else asm volatile("cp.async.commit_group;\n");

    for (int kt = 0; kt < nk; kt++) {
        const int s = kt & 3;
        asm volatile("cp.async.wait_group 1;\n" ::: "memory");
        __syncthreads();

        if (kt + 3 < nk) load_stage(kt + 3);
        else asm volatile("cp.async.commit_group;\n");

        unsigned afr[2][4];
#pragma unroll
        for (int mt = 0; mt < 2; mt++) {
            int m = wm + mt * 16 + gid;
            afr[mt][0] = As[s][m    ][tig];
            afr[mt][1] = As[s][m + 8][tig];
            afr[mt][2] = As[s][m    ][tig + 4];
            afr[mt][3] = As[s][m + 8][tig + 4];
        }
        unsigned bfr[8][2];
#pragma unroll
        for (int ntp = 0; ntp < 4; ntp++) {
            int ncg = (wn >> 3) + ntp * 2 + lnc;
            int chunk = ncg ^ (lk & 7);
            unsigned addr = bs_base + s * 4096 + lk * 256 + chunk * 16;
            unsigned r0, r1, r2, r3;
            asm volatile(
                "ldmatrix.sync.aligned.m8n8.x4.trans.shared.b16 {%0,%1,%2,%3}, [%4];"
                : "=r"(r0), "=r"(r1), "=r"(r2), "=r"(r3) : "r"(addr));
            bfr[ntp * 2    ][0] = r0;
            bfr[ntp * 2    ][1] = r1;
            bfr[ntp * 2 + 1][0] = r2;
            bfr[ntp * 2 + 1][1] = r3;
        }
#pragma unroll
        for (int mt = 0; mt < 2; mt++)
#pragma unroll
            for (int nt = 0; nt < 8; nt++)
                mma_f16(acc[mt][nt], afr[mt], bfr[nt]);
    }

#pragma unroll
    for (int nt = 0; nt < 8; nt++) {
        const int cc = col0 + wn + nt * 8 + 2 * tig;
        float2 bv = *(const float2*)&bias[cc];
#pragma unroll
        for (int mt = 0; mt < 2; mt++) {
            int r0 = row0 + wm + mt * 16 + gid;
#pragma unroll
            for (int half_ = 0; half_ < 2; half_++) {
                int rr = r0 + half_ * 8;
                float vx = acc[mt][nt][half_ * 2 + 0] + bv.x;
                float vy = acc[mt][nt][half_ * 2 + 1] + bv.y;
                if (mode == 0) {
                    *(__half2*)&Ch[(long)rr * N + cc] = __floats2half2_rn(vx, vy);
                } else if (mode == 1) {
                    float2 rrv = *(const float2*)&R[(long)rr * N + cc];
                    *(float2*)&Cf[(long)rr * N + cc] = make_float2(vx + rrv.x, vy + rrv.y);
                } else {
                    float t0 = vx, t1 = vy;
                    vx = 0.5f * t0 * (1.f + tanhf(0.7978845608028654f * (t0 + 0.044715f * t0 * t0 * t0)));
                    vy = 0.5f * t1 * (1.f + tanhf(0.7978845608028654f * (t1 + 0.044715f * t1 * t1 * t1)));
                    *(__half2*)&Ch[(long)rr * N + cc] = __floats2half2_rn(vx, vy);
                }
            }
        }
    }
}

// ---------------- layernorm over H=768 ----------------
__global__ void __launch_bounds__(256)
ln_kernel(const float* __restrict__ in, const float* __restrict__ g,
          const float* __restrict__ b, float* __restrict__ out, __half* __restrict__ outh)
{
    const int row = blockIdx.x;
    const float* x = in + (long)row * HH;
    float v0[3];
    float s = 0.f, s2 = 0.f;
#pragma unroll
    for (int i = 0; i < 3; i++) {
        float t = x[threadIdx.x + i * 256];
        v0[i] = t; s += t; s2 += t * t;
    }
#pragma unroll
    for (int o = 16; o > 0; o >>= 1) {
        s  += __shfl_xor_sync(0xffffffffu, s, o);
        s2 += __shfl_xor_sync(0xffffffffu, s2, o);
    }
    __shared__ float red0[8], red1[8];
    int w = threadIdx.x >> 5;
    if ((threadIdx.x & 31) == 0) { red0[w] = s; red1[w] = s2; }
    __syncthreads();
    if (threadIdx.x < 32) {
        s  = (threadIdx.x < 8) ? red0[threadIdx.x] : 0.f;
        s2 = (threadIdx.x < 8) ? red1[threadIdx.x] : 0.f;
#pragma unroll
        for (int o = 4; o > 0; o >>= 1) {
            s  += __shfl_xor_sync(0xffffffffu, s, o);
            s2 += __shfl_xor_sync(0xffffffffu, s2, o);
        }
        if (threadIdx.x == 0) { red0[0] = s; red1[0] = s2; }
    }
    __syncthreads();
    float mean = red0[0] * (1.f / HH);
    float var  = red1[0] * (1.f / HH) - mean * mean;
    float rstd = rsqrtf(var + 1e-5f);
#pragma unroll
    for (int i = 0; i < 3; i++) {
        int c = threadIdx.x + i * 256;
        float val = (v0[i] - mean) * rstd * g[c] + b[c];
        out [(long)row * HH + c] = val;
        outh[(long)row * HH + c] = __float2half(val);
    }
}

// ---------------- banded attention via mma (fp16 qkv) ----------------
__global__ void __launch_bounds__(256)
band_attn_kernel(const __half* __restrict__ qkv, __half* __restrict__ o)
{
    const int n = blockIdx.x, h = blockIdx.y, b = blockIdx.z;
    const int tid  = threadIdx.x;
    const int w    = tid >> 5;
    const int lane = tid & 31;
    const int gid  = lane >> 2;
    const int tig  = lane & 3;

    __shared__ __align__(16) char smem[2][2][64 * 128];
    const unsigned smem_base = (unsigned)__cvta_generic_to_shared(&smem[0][0][0]);

    const int s_q0 = n * CW + w * 16 + gid;
    const int s_q1 = s_q0 + 8;

    unsigned qf[4][4];
    {
        const __half* q0 = qkv + ((long)(b * SS + s_q0) * QKVW + h * DD);
        const __half* q1 = qkv + ((long)(b * SS + s_q1) * QKVW + h * DD);
#pragma unroll
        for (int kk = 0; kk < 4; kk++) {
            int d0 = kk * 16 + 2 * tig;
            qf[kk][0] = *(const unsigned*)(q0 + d0);
            qf[kk][1] = *(const unsigned*)(q1 + d0);
            qf[kk][2] = *(const unsigned*)(q0 + d0 + 8);
            qf[kk][3] = *(const unsigned*)(q1 + d0 + 8);
        }
    }

    float m0 = -1e30f, m1 = -1e30f, l0 = 0.f, l1 = 0.f;
    float accO[8][4];
#pragma unroll
    for (int dt = 0; dt < 8; dt++)
#pragma unroll
        for (int u = 0; u < 4; u++) accO[dt][u] = 0.f;

    auto fill = [&](int t) {
        const int buf = t & 1;
#pragma unroll
        for (int i = 0; i < 4; i++) {
            int g = tid + i * 256;
            int tensor = g >> 9;
            int within = g & 511;
            int row = within >> 3;
            int c   = within & 7;
            int p  = (t == 6) ? row : (n * CW - CW + t * 64 + row);
            int pc = min(max(p, 0), SS - 1);
            const __half* src = qkv + ((long)(b * SS + pc) * QKVW + (tensor ? 2 * HH : HH) + h * DD + c * 8);
            unsigned dst = smem_base + buf * 16384 + tensor * 8192 + row * 128 + (((unsigned)(c ^ (row & 7))) << 4);
            cp16(dst, src);
        }
        asm volatile("cp.async.commit_group;\n");
    };

    fill(0);

    for (int t = 0; t < 7; t++) {
        const int buf = t & 1;
        if (t + 1 < 7) {
            fill(t + 1);
            asm volatile("cp.async.wait_group 1;\n" ::: "memory");
        } else {
            asm volatile("cp.async.wait_group 0;\n" ::: "memory");
        }
        __syncthreads();

        const unsigned kb = smem_base + buf * 16384;
        const unsigned vb = kb + 8192;

        float s[8][4];
#pragma unroll
        for (int ng = 0; ng < 8; ng++)
#pragma unroll
            for (int u = 0; u < 4; u++) s[ng][u] = 0.f;

#pragma unroll
        for (int ng = 0; ng < 8; ng++) {
#pragma unroll
            for (int kp = 0; kp < 2; kp++) {
                int row = ng * 8 + (lane & 7);
                int ci  = kp * 4 + (lane >> 3);
                unsigned addr = kb + row * 128 + (((unsigned)(ci ^ (row & 7))) << 4);
                unsigned r0, r1, r2, r3;
                asm volatile(
                    "ldmatrix.sync.aligned.m8n8.x4.shared.b16 {%0,%1,%2,%3}, [%4];"
                    : "=r"(r0), "=r"(r1), "=r"(r2), "=r"(r3) : "r"(addr));
                unsigned bf0[2] = {r0, r1};
                unsigned bf1[2] = {r2, r3};
                mma_f16(s[ng], qf[kp * 2],     bf0);
                mma_f16(s[ng], qf[kp * 2 + 1], bf1);
            }
        }

        const int p00 = (t == 6) ? 0 : (n * CW - CW + t * 64);
#pragma unroll
        for (int ng = 0; ng < 8; ng++) {
            int k0 = ng * 8 + 2 * tig;
            int p0v = p00 + k0;
            int p1v = p0v + 1;
            bool v00, v01, v10, v11;
            if (t == 6) {
                v00 = v10 = (k0 < GT);
                v01 = v11 = (k0 + 1 < GT);
            } else {
                bool base0 = (p0v >= GT) && (p0v < SS);
                bool base1 = (p1v >= GT) && (p1v < SS);
                v00 = base0 && (abs(p0v - s_q0) <= CW);
                v10 = base0 && (abs(p0v - s_q1) <= CW);
                v01 = base1 && (abs(p1v - s_q0) <= CW);
                v11 = base1 && (abs(p1v - s_q1) <= CW);
            }
            if (!v00) s[ng][0] = -1e30f;
            if (!v01) s[ng][1] = -1e30f;
            if (!v10) s[ng][2] = -1e30f;
            if (!v11) s[ng][3] = -1e30f;
        }

        float t0 = -1e30f, t1 = -1e30f;
#pragma unroll
        for (int ng = 0; ng < 8; ng++) {
            t0 = fmaxf(t0, fmaxf(s[ng][0], s[ng][1]));
            t1 = fmaxf(t1, fmaxf(s[ng][2], s[ng][3]));
        }
        t0 = fmaxf(t0, __shfl_xor_sync(0xffffffffu, t0, 1));
        t0 = fmaxf(t0, __shfl_xor_sync(0xffffffffu, t0, 2));
        t1 = fmaxf(t1, __shfl_xor_sync(0xffffffffu, t1, 1));
        t1 = fmaxf(t1, __shfl_xor_sync(0xffffffffu, t1, 2));

        float mn0 = fmaxf(m0, t0), mn1 = fmaxf(m1, t1);
        float al0 = __expf(m0 - mn0), al1 = __expf(m1 - mn1);
        l0 *= al0; l1 *= al1;
#pragma unroll
        for (int dt = 0; dt < 8; dt++) {
            accO[dt][0] *= al0; accO[dt][1] *= al0;
            accO[dt][2] *= al1; accO[dt][3] *= al1;
        }

        unsigned ph[8][2];
#pragma unroll
        for (int ng = 0; ng < 8; ng++) {
            float p0 = (s[ng][0] < -1e29f) ? 0.f : __expf(s[ng][0] - mn0);
            float p1 = (s[ng][1] < -1e29f) ? 0.f : __expf(s[ng][1] - mn0);
            float p2 = (s[ng][2] < -1e29f) ? 0.f : __expf(s[ng][2] - mn1);
            float p3 = (s[ng][3] < -1e29f) ? 0.f : __expf(s[ng][3] - mn1);
            l0 += p0 + p1;
            l1 += p2 + p3;
            __half2 h01 = __floats2half2_rn(p0, p1);
            __half2 h23 = __floats2half2_rn(p2, p3);
            ph[ng][0] = *reinterpret_cast<unsigned*>(&h01);
            ph[ng][1] = *reinterpret_cast<unsigned*>(&h23);
        }
        m0 = mn0; m1 = mn1;

        const int lsel = lane >> 3;
        const int lk   = (lsel & 1) * 8 + (lane & 7);
        const int lnc  = lsel >> 1;
#pragma unroll
        for (int kk = 0; kk < 4; kk++) {
            unsigned af[4] = { ph[2 * kk][0], ph[2 * kk][1], ph[2 * kk + 1][0], ph[2 * kk + 1][1] };
#pragma unroll
            for (int dp = 0; dp < 4; dp++) {
                int row = kk * 16 + lk;
                int ci  = (dp * 2 + lnc) ^ (row & 7);
                unsigned addr = vb + row * 128 + (((unsigned)ci) << 4);
                unsigned r0, r1, r2, r3;
                asm volatile(
                    "ldmatrix.sync.aligned.m8n8.x4.trans.shared.b16 {%0,%1,%2,%3}, [%4];"
                    : "=r"(r0), "=r"(r1), "=r"(r2), "=r"(r3) : "r"(addr));
                unsigned b0[2] = {r0, r1};
                unsigned b1[2] = {r2, r3};
                mma_f16(accO[dp * 2],     af, b0);
                mma_f16(accO[dp * 2 + 1], af, b1);
            }
        }
        __syncthreads();
    }

    l0 += __shfl_xor_sync(0xffffffffu, l0, 1);
    l0 += __shfl_xor_sync(0xffffffffu, l0, 2);
    l1 += __shfl_xor_sync(0xffffffffu, l1, 1);
    l1 += __shfl_xor_sync(0xffffffffu, l1, 2);
    float i0 = 1.f / l0, i1 = 1.f / l1;

    __half* o0 = o + ((long)(b * SS + s_q0) * HH + h * DD);
    __half* o1 = o + ((long)(b * SS + s_q1) * HH + h * DD);
#pragma unroll
    for (int dt = 0; dt < 8; dt++) {
        int d0 = dt * 8 + 2 * tig;
        *(__half2*)(o0 + d0) = __floats2half2_rn(accO[dt][0] * i0, accO[dt][1] * i0);
        *(__half2*)(o1 + d0) = __floats2half2_rn(accO[dt][2] * i1, accO[dt][3] * i1);
    }
}

// ---------------- global-query attention (fp16 qkv) ----------------
__global__ void __launch_bounds__(128)
glob_attn_kernel(const __half* __restrict__ qkv, __half* __restrict__ o)
{
    const int g = blockIdx.x, h = blockIdx.y, b = blockIdx.z;
    const int tid = threadIdx.x;

    __shared__ float qs[DD];
    __shared__ float sc[SS];
    __shared__ float red[4];
    __shared__ float part[4][DD];

    if (tid < DD) qs[tid] = __half2float(qkv[(long)(b * SS + g) * QKVW + h * DD + tid]);
    __syncthreads();

    float lm = -1e30f;
    for (int s = tid; s < SS; s += 128) {
        const __half* kr = qkv + ((long)(b * SS + s) * QKVW + HH + h * DD);
        float acc = 0.f;
#pragma unroll
        for (int c = 0; c < 8; c++) {
            uint4 raw = *(const uint4*)(kr + c * 8);
            __half2* hp = (__half2*)&raw;
#pragma unroll
            for (int u = 0; u < 4; u++) {
                float2 kf = __half22float2(hp[u]);
                acc += qs[c * 8 + 2 * u] * kf.x + qs[c * 8 + 2 * u + 1] * kf.y;
            }
        }
        sc[s] = acc;
        lm = fmaxf(lm, acc);
    }
#pragma unroll
    for (int off = 16; off > 0; off >>= 1)
        lm = fmaxf(lm, __shfl_xor_sync(0xffffffffu, lm, off));
    if ((tid & 31) == 0) red[tid >> 5] = lm;
    __syncthreads();
    float m = fmaxf(fmaxf(red[0], red[1]), fmaxf(red[2], red[3]));

    float ls = 0.f;
    for (int s = tid; s < SS; s += 128) {
        float e = __expf(sc[s] - m);
        sc[s] = e;
        ls += e;
    }
#pragma unroll
    for (int off = 16; off > 0; off >>= 1)
        ls += __shfl_xor_sync(0xffffffffu, ls, off);
    __syncthreads();
    if ((tid & 31) == 0) red[tid >> 5] = ls;
    __syncthreads();
    float l = red[0] + red[1] + red[2] + red[3];

    const int d2  = (tid & 31) * 2;
    const int grp = tid >> 5;
    float2 acc2 = make_float2(0.f, 0.f);
    const __half* vp = qkv + ((long)(b * SS) * QKVW + 2 * HH + h * DD + d2);
    const int s0 = grp * (SS / 4);
    for (int s = s0; s < s0 + SS / 4; s++) {
        __half2 hv = *(const __half2*)(vp + (long)s * QKVW);
        float2 f = __half22float2(hv);
        acc2.x += sc[s] * f.x;
        acc2.y += sc[s] * f.y;
    }
    part[grp][d2]     = acc2.x;
    part[grp][d2 + 1] = acc2.y;
    __syncthreads();
    if (tid < DD) {
        float inv = 1.f / l;
        float v = (part[0][tid] + part[1][tid] + part[2][tid] + part[3][tid]) * inv;
        o[(long)(b * SS + g) * HH + h * DD + tid] = __float2half(v);
    }
}

// ---------------- pair gather + classifier head ----------------
__global__ void __launch_bounds__(128)
head_kernel(const float* __restrict__ x, const int* __restrict__ pairs,
            const float* __restrict__ Wh, const float* __restrict__ bh,
            float* __restrict__ out)
{
    const int bp = blockIdx.x;
    const int b = bp >> 7;
    const int i = pairs[bp * 2 + 0];
    const int j = pairs[bp * 2 + 1];
    const float* xi = x + (long)(b * SS + i) * HH;
    const float* xj = x + (long)(b * SS + j) * HH;

    float acc[NLC] = {0.f, 0.f, 0.f};
    for (int d = threadIdx.x; d < 2 * HH; d += 128) {
        float e = (d < HH) ? xi[d] : xj[d - HH];
        acc[0] += e * Wh[d * NLC + 0];
        acc[1] += e * Wh[d * NLC + 1];
        acc[2] += e * Wh[d * NLC + 2];
    }
#pragma unroll
    for (int o = 16; o > 0; o >>= 1) {
#pragma unroll
        for (int c = 0; c < NLC; c++)
            acc[c] += __shfl_xor_sync(0xffffffffu, acc[c], o);
    }
    __shared__ float sm[NLC][4];
    int w = threadIdx.x >> 5;
    if ((threadIdx.x & 31) == 0) {
#pragma unroll
        for (int c = 0; c < NLC; c++) sm[c][w] = acc[c];
    }
    __syncthreads();
    if (threadIdx.x < NLC) {
        float s = sm[threadIdx.x][0] + sm[threadIdx.x][1] + sm[threadIdx.x][2] + sm[threadIdx.x][3];
        out[bp * NLC + threadIdx.x] = s + bh[threadIdx.x];
    }
}

// ---------------- host orchestration ----------------
extern "C" void kernel_launch(void* const* d_in, const int* in_sizes, int n_in,
                              void* d_out, int out_size)
{
    const int*   input_ids    = (const int*)  d_in[0];
    const int*   pair_indices = (const int*)  d_in[1];
    const float* emb          = (const float*)d_in[2];
    const float* Wq  = (const float*)d_in[3];
    const float* bq  = (const float*)d_in[4];
    const float* Wk  = (const float*)d_in[5];
    const float* bk  = (const float*)d_in[6];
    const float* Wv  = (const float*)d_in[7];
    const float* bv  = (const float*)d_in[8];
    const float* Wo  = (const float*)d_in[9];
    const float* bo  = (const float*)d_in[10];
    const float* ln1g = (const float*)d_in[11];
    const float* ln1b = (const float*)d_in[12];
    const float* Wf1 = (const float*)d_in[13];
    const float* bf1 = (const float*)d_in[14];
    const float* Wf2 = (const float*)d_in[15];
    const float* bf2 = (const float*)d_in[16];
    const float* ln2g = (const float*)d_in[17];
    const float* ln2b = (const float*)d_in[18];
    const float* Wh  = (const float*)d_in[19];
    const float* bh  = (const float*)d_in[20];
    float* out = (float*)d_out;

    float *x, *tb, *bqkv;
    __half *qkvh, *xh, *o16, *h16, *wbuf;
    cudaGetSymbolAddress((void**)&x,    g_x);
    cudaGetSymbolAddress((void**)&tb,   g_t);
    cudaGetSymbolAddress((void**)&bqkv, g_bqkv);
    cudaGetSymbolAddress((void**)&qkvh, g_qkvh);
    cudaGetSymbolAddress((void**)&xh,   g_xh);
    cudaGetSymbolAddress((void**)&o16,  g_o16);
    cudaGetSymbolAddress((void**)&h16,  g_h16);
    cudaGetSymbolAddress((void**)&wbuf, g_wbuf);

    long nQKV = (long)LL * HH * QKVW;
    int  nHH  = LL * HH * HH;
    int  nFF  = LL * HH * FF;

    const dim3 gQKV(QKVW / GN, MROWS / GM);     // 18 x 32
    const dim3 gFF (FF   / GN, MROWS / GM);     // 24 x 32
    const dim3 gHHs(HH   / GN, MROWS / 64);     //  6 x 64 = 384 CTAs (small-tile kernel)
    const dim3 attnGrid(SS / CW, NHH, BB);
    const dim3 globGrid(GT, NHH, BB);

    // launches 0..3: embed, pack_qkv, pack_bqkv, gemmQKV  (ncu capture = index 3)
    {
        int total = MROWS * HH;
        embed_kernel<<<(total + 255) / 256, 256>>>(input_ids, emb, x, xh);
        pack_qkv_kernel<<<(int)((nQKV / 8 + 255) / 256), 256>>>(Wq, Wk, Wv, wbuf + WQKVOFF);
        pack_bqkv_kernel<<<(LL * QKVW + 255) / 256, 256>>>(bq, bk, bv, bqkv);
    }

    for (int l = 0; l < LL; l++) {
        const __half* wqkv = wbuf + WQKVOFF + (long)l * HH * QKVW;
        const __half* wo   = wbuf + WOOFF   + (long)l * HH * HH;
        const __half* w1   = wbuf + WF1OFF  + (long)l * HH * FF;
        const __half* w2   = wbuf + WF2OFF  + (long)l * FF * HH;

        gemm16_kernel<<<gQKV, 256>>>(xh, wqkv, bqkv + l * QKVW, nullptr, nullptr, qkvh, MROWS, QKVW, HH, 0);

        if (l == 0) {
            f2h_kernel<<<(nHH / 8 + 255) / 256, 256>>>(Wo,  wbuf + WOOFF,  nHH);
            f2h_kernel<<<(nFF / 8 + 255) / 256, 256>>>(Wf1, wbuf + WF1OFF, nFF);
            f2h_kernel<<<(nFF / 8 + 255) / 256, 256>>>(Wf2, wbuf + WF2OFF, nFF);
        }

        band_attn_kernel<<<attnGrid, 256>>>(qkvh, o16);
        glob_attn_kernel<<<globGrid, 128>>>(qkvh, o16);

        gemm16s_kernel<<<gHHs, 128>>>(o16, wo, bo + l * HH, x, tb, nullptr, MROWS, HH, HH, 1);
        ln_kernel<<<MROWS, 256>>>(tb, ln1g + l * HH, ln1b + l * HH, x, xh);

        gemm16_kernel<<<gFF, 256>>>(xh, w1, bf1 + l * FF, nullptr, nullptr, h16, MROWS, FF, HH, 2);
        gemm16s_kernel<<<gHHs, 128>>>(h16, w2, bf2 + l * HH, x, tb, nullptr, MROWS, HH, FF, 1);
        ln_kernel<<<MROWS, 256>>>(tb, ln2g + l * HH, ln2b + l * HH, x, xh);
    }

    head_kernel<<<BB * PP, 128>>>(x, pair_indices, Wh, bh, out);
}

// round 16
// speedup vs baseline: 1.1917x; 1.0929x over previous
#include <cuda_runtime.h>
#include <cuda_fp16.h>
#include <math.h>
#include <stdint.h>

// ---------------- problem constants ----------------
#define BB 2
#define SS 2048
#define HH 768
#define NHH 12
#define DD 64
#define LL 4
#define CW 128
#define GT 16
#define PP 128
#define NLC 3
#define FF (4*HH)
#define MROWS (BB*SS)
#define QKVW (3*HH)   // 2304

// ---------------- scratch ----------------
__device__ float  g_x   [MROWS*HH];
__device__ float  g_t   [MROWS*HH];
__device__ __half g_qkvh[MROWS*QKVW];
__device__ __half g_xh  [MROWS*HH];
__device__ __half g_o16 [MROWS*HH];
__device__ __half g_h16 [MROWS*FF];
__device__ float  g_bqkv[LL*QKVW];
#define WQKVOFF 0
#define WOOFF   (3*LL*HH*HH)
#define WF1OFF  (4*LL*HH*HH)
#define WF2OFF  (4*LL*HH*HH + LL*HH*FF)
#define WTOTAL  (4*LL*HH*HH + 2*LL*HH*FF)
__device__ __half g_wbuf[WTOTAL];

// ---------------- fp32 -> fp16 bulk convert ----------------
__global__ void f2h_kernel(const float* __restrict__ s, __half* __restrict__ d, int n)
{
    int i = (blockIdx.x * 256 + threadIdx.x) * 8;
    if (i >= n) return;
    float4 v0 = *(const float4*)&s[i];
    float4 v1 = *(const float4*)&s[i + 4];
    __half2 h0 = __floats2half2_rn(v0.x, v0.y);
    __half2 h1 = __floats2half2_rn(v0.z, v0.w);
    __half2 h2 = __floats2half2_rn(v1.x, v1.y);
    __half2 h3 = __floats2half2_rn(v1.z, v1.w);
    uint4 o;
    o.x = *reinterpret_cast<unsigned*>(&h0);
    o.y = *reinterpret_cast<unsigned*>(&h1);
    o.z = *reinterpret_cast<unsigned*>(&h2);
    o.w = *reinterpret_cast<unsigned*>(&h3);
    *(uint4*)&d[i] = o;
}

// ---------------- pack Wq|Wk|Wv -> [L][H][2304] fp16, scale q by 0.125 ----------------
__global__ void pack_qkv_kernel(const float* __restrict__ Wq, const float* __restrict__ Wk,
                                const float* __restrict__ Wv, __half* __restrict__ dst)
{
    long i = ((long)blockIdx.x * 256 + threadIdx.x) * 8;
    if (i >= (long)LL * HH * QKVW) return;
    int l   = (int)(i / (HH * QKVW));
    int rem = (int)(i - (long)l * HH * QKVW);
    int k   = rem / QKVW;
    int j   = rem - k * QKVW;
    int seg = j / HH;
    int jj  = j - seg * HH;
    const float* src = (seg == 0 ? Wq : seg == 1 ? Wk : Wv) + ((long)l * HH + k) * HH + jj;
    float sc = (seg == 0) ? 0.125f : 1.0f;
    float4 v0 = *(const float4*)&src[0];
    float4 v1 = *(const float4*)&src[4];
    __half2 h0 = __floats2half2_rn(v0.x * sc, v0.y * sc);
    __half2 h1 = __floats2half2_rn(v0.z * sc, v0.w * sc);
    __half2 h2 = __floats2half2_rn(v1.x * sc, v1.y * sc);
    __half2 h3 = __floats2half2_rn(v1.z * sc, v1.w * sc);
    uint4 o;
    o.x = *reinterpret_cast<unsigned*>(&h0);
    o.y = *reinterpret_cast<unsigned*>(&h1);
    o.z = *reinterpret_cast<unsigned*>(&h2);
    o.w = *reinterpret_cast<unsigned*>(&h3);
    *(uint4*)&dst[i] = o;
}

__global__ void pack_bqkv_kernel(const float* __restrict__ bq, const float* __restrict__ bk,
                                 const float* __restrict__ bv, float* __restrict__ dst)
{
    int i = blockIdx.x * 256 + threadIdx.x;
    if (i >= LL * QKVW) return;
    int l = i / QKVW;
    int j = i - l * QKVW;
    int seg = j / HH;
    int jj  = j - seg * HH;
    dst[i] = (seg == 0 ? bq[l * HH + jj] * 0.125f : seg == 1 ? bk[l * HH + jj] : bv[l * HH + jj]);
}

// ---------------- embedding gather ----------------
__global__ void embed_kernel(const int* __restrict__ ids,
                             const float* __restrict__ emb,
                             float* __restrict__ x, __half* __restrict__ xh)
{
    int idx = blockIdx.x * blockDim.x + threadIdx.x;
    if (idx >= MROWS * HH) return;
    int tok = idx / HH;
    int d   = idx - tok * HH;
    float e = emb[(long)ids[tok] * HH + d];
    x[idx]  = e;
    xh[idx] = __float2half(e);
}

// ---------------- shared mma helpers ----------------
__device__ __forceinline__ void mma_f16(float* d, const unsigned* a, const unsigned* b) {
    asm volatile(
        "mma.sync.aligned.m16n8k16.row.col.f32.f16.f16.f32 "
        "{%0,%1,%2,%3}, {%4,%5,%6,%7}, {%8,%9}, {%0,%1,%2,%3};\n"
        : "+f"(d[0]), "+f"(d[1]), "+f"(d[2]), "+f"(d[3])
        : "r"(a[0]), "r"(a[1]), "r"(a[2]), "r"(a[3]),
          "r"(b[0]), "r"(b[1]));
}

__device__ __forceinline__ void cp16(unsigned smem, const void* g) {
    asm volatile("cp.async.cg.shared.global [%0], [%1], 16;\n" :: "r"(smem), "l"(g));
}

// ---------------- fp16 GEMM, CTA 128x128, 256 thr ----------------
// mode 0: Ch = AW+b (fp16); mode 1: Cf = AW+b+R; mode 2: Ch = gelu(AW+b)
#define GM 128
#define GN 128
#define NST 4

__global__ void __launch_bounds__(256, 2)
gemm16_kernel(const __half* __restrict__ A, const __half* __restrict__ W,
              const float* __restrict__ bias, const float* __restrict__ R,
              float* __restrict__ Cf, __half* __restrict__ Ch,
              int M, int N, int K, int mode)
{
    __shared__ unsigned As[NST][GM][12];
    __shared__ __half Bs[NST][16][GN];

    const int tid  = threadIdx.x;
    const int w    = tid >> 5;
    const int lane = tid & 31;
    const int gid  = lane >> 2;
    const int tig  = lane & 3;
    const int wm   = (w >> 1) * 32;
    const int wn   = (w & 1) * 64;
    const int row0 = blockIdx.y * GM;
    const int col0 = blockIdx.x * GN;

    const int ar = tid >> 1;
    const int ac = tid & 1;
    const int bk = tid >> 4;
    const int bc = tid & 15;
    const int bcs = bc ^ (bk & 7);

    const unsigned as_base = (unsigned)__cvta_generic_to_shared(&As[0][0][0]);
    const unsigned bs_base = (unsigned)__cvta_generic_to_shared(&Bs[0][0][0]);
    const unsigned a_dst0 = as_base + (ar * 12 + ac * 4) * 4;
    const unsigned b_dst0 = bs_base + bk * 256 + bcs * 16;

    const long arow_base = (long)(row0 + ar) * K + ac * 8;
    const long brow_col  = (long)col0 + bc * 8;

    const int lsel = lane >> 3;
    const int lk   = (lsel & 1) * 8 + (lane & 7);
    const int lnc  = (lsel >> 1);
    // ldmatrix A lane mapping: row within m16 tile, k-half
    const int amrow = (lane & 7) + (lsel & 1) * 8;
    const int akh   = lsel >> 1;

    float acc[2][8][4];
#pragma unroll
    for (int mt = 0; mt < 2; mt++)
#pragma unroll
        for (int nt = 0; nt < 8; nt++)
#pragma unroll
            for (int u = 0; u < 4; u++) acc[mt][nt][u] = 0.f;

    const int nk = K / 16;

    auto load_stage = [&](int kt) {
        const int s = kt & 3;
        cp16(a_dst0 + s * 6144, &A[arow_base + kt * 16]);
        cp16(b_dst0 + s * 4096, &W[(long)(kt * 16 + bk) * N + brow_col]);
        asm volatile("cp.async.commit_group;\n");
    };

    load_stage(0);
    if (nk > 1) load_stage(1); else asm volatile("cp.async.commit_group;\n");
    if (nk > 2) load_stage(2); else asm volatile("cp.async.commit_group;\n");

    for (int kt = 0; kt < nk; kt++) {
        const int s = kt & 3;
        asm volatile("cp.async.wait_group 1;\n" ::: "memory");
        __syncthreads();

        if (kt + 3 < nk) load_stage(kt + 3);
        else asm volatile("cp.async.commit_group;\n");

        unsigned afr[2][4];
#pragma unroll
        for (int mt = 0; mt < 2; mt++) {
            unsigned addr = as_base + s * 6144 + (wm + mt * 16 + amrow) * 48 + akh * 16;
            asm volatile(
                "ldmatrix.sync.aligned.m8n8.x4.shared.b16 {%0,%1,%2,%3}, [%4];"
                : "=r"(afr[mt][0]), "=r"(afr[mt][1]), "=r"(afr[mt][2]), "=r"(afr[mt][3])
                : "r"(addr));
        }
        unsigned bfr[8][2];
#pragma unroll
        for (int ntp = 0; ntp < 4; ntp++) {
            int ncg = (wn >> 3) + ntp * 2 + lnc;
            int chunk = ncg ^ (lk & 7);
            unsigned addr = bs_base + s * 4096 + lk * 256 + chunk * 16;
            unsigned r0, r1, r2, r3;
            asm volatile(
                "ldmatrix.sync.aligned.m8n8.x4.trans.shared.b16 {%0,%1,%2,%3}, [%4];"
                : "=r"(r0), "=r"(r1), "=r"(r2), "=r"(r3) : "r"(addr));
            bfr[ntp * 2    ][0] = r0;
            bfr[ntp * 2    ][1] = r1;
            bfr[ntp * 2 + 1][0] = r2;
            bfr[ntp * 2 + 1][1] = r3;
        }
#pragma unroll
        for (int mt = 0; mt < 2; mt++)
#pragma unroll
            for (int nt = 0; nt < 8; nt++)
                mma_f16(acc[mt][nt], afr[mt], bfr[nt]);
    }

#pragma unroll
    for (int nt = 0; nt < 8; nt++) {
        const int cc = col0 + wn + nt * 8 + 2 * tig;
        float2 bv = *(const float2*)&bias[cc];
#pragma unroll
        for (int mt = 0; mt < 2; mt++) {
            int r0 = row0 + wm + mt * 16 + gid;
#pragma unroll
            for (int half_ = 0; half_ < 2; half_++) {
                int rr = r0 + half_ * 8;
                float vx = acc[mt][nt][half_ * 2 + 0] + bv.x;
                float vy = acc[mt][nt][half_ * 2 + 1] + bv.y;
                if (mode == 0) {
                    *(__half2*)&Ch[(long)rr * N + cc] = __floats2half2_rn(vx, vy);
                } else if (mode == 1) {
                    float2 rrv = *(const float2*)&R[(long)rr * N + cc];
                    *(float2*)&Cf[(long)rr * N + cc] = make_float2(vx + rrv.x, vy + rrv.y);
                } else {
                    float t0 = vx, t1 = vy;
                    vx = 0.5f * t0 * (1.f + tanhf(0.7978845608028654f * (t0 + 0.044715f * t0 * t0 * t0)));
                    vy = 0.5f * t1 * (1.f + tanhf(0.7978845608028654f * (t1 + 0.044715f * t1 * t1 * t1)));
                    *(__half2*)&Ch[(long)rr * N + cc] = __floats2half2_rn(vx, vy);
                }
            }
        }
    }
}

// ---------------- fp16 GEMM variant: CTA 64x128, 128 thr (N=768 GEMMs) ----------------
__global__ void __launch_bounds__(128, 4)
gemm16s_kernel(const __half* __restrict__ A, const __half* __restrict__ W,
               const float* __restrict__ bias, const float* __restrict__ R,
               float* __restrict__ Cf, __half* __restrict__ Ch,
               int M, int N, int K, int mode)
{
    __shared__ unsigned As[NST][64][12];
    __shared__ __half Bs[NST][16][GN];

    const int tid  = threadIdx.x;
    const int w    = tid >> 5;
    const int lane = tid & 31;
    const int gid  = lane >> 2;
    const int tig  = lane & 3;
    const int wm   = (w >> 1) * 32;
    const int wn   = (w & 1) * 64;
    const int row0 = blockIdx.y * 64;
    const int col0 = blockIdx.x * GN;

    const int ar = tid >> 1;
    const int ac = tid & 1;
    const int bk = tid >> 4;
    const int bc = tid & 15;
    const int bcs = bc ^ (bk & 7);

    const unsigned as_base = (unsigned)__cvta_generic_to_shared(&As[0][0][0]);
    const unsigned bs_base = (unsigned)__cvta_generic_to_shared(&Bs[0][0][0]);
    const unsigned a_dst0 = as_base + (ar * 12 + ac * 4) * 4;
    const unsigned b_dst0 = bs_base + bk * 256 + bcs * 16;

    const long arow_base = (long)(row0 + ar) * K + ac * 8;
    const long brow_col  = (long)col0 + bc * 8;

    const int lsel = lane >> 3;
    const int lk   = (lsel & 1) * 8 + (lane & 7);
    const int lnc  = (lsel >> 1);
    const int amrow = (lane & 7) + (lsel & 1) * 8;
    const int akh   = lsel >> 1;

    float acc[2][8][4];
#pragma unroll
    for (int mt = 0; mt < 2; mt++)
#pragma unroll
        for (int nt = 0; nt < 8; nt++)
#pragma unroll
            for (int u = 0; u < 4; u++) acc[mt][nt][u] = 0.f;

    const int nk = K / 16;

    auto load_stage = [&](int kt) {
        const int s = kt & 3;
        cp16(a_dst0 + s * 3072, &A[arow_base + kt * 16]);
        cp16(b_dst0 + s * 4096,        &W[(long)(kt * 16 + bk)     * N + brow_col]);
        cp16(b_dst0 + s * 4096 + 2048, &W[(long)(kt * 16 + bk + 8) * N + brow_col]);
        asm volatile("cp.async.commit_group;\n");
    };

    load_stage(0);
    if (nk > 1) load_stage(1); else asm volatile("cp.async.commit_group;\n");
    if (nk > 2) load_stage(2); else asm volatile("cp.async.commit_group;\n");

    for (int kt = 0; kt < nk; kt++) {
        const int s = kt & 3;
        asm volatile("cp.async.wait_group 1;\n" ::: "memory");
        __syncthreads();

        if (kt + 3 < nk) load_stage(kt + 3);
        else asm volatile("cp.async.commit_group;\n");

        unsigned afr[2][4];
#pragma unroll
        for (int mt = 0; mt < 2; mt++) {
            unsigned addr = as_base + s * 3072 + (wm + mt * 16 + amrow) * 48 + akh * 16;
            asm volatile(
                "ldmatrix.sync.aligned.m8n8.x4.shared.b16 {%0,%1,%2,%3}, [%4];"
                : "=r"(afr[mt][0]), "=r"(afr[mt][1]), "=r"(afr[mt][2]), "=r"(afr[mt][3])
                : "r"(addr));
        }
        unsigned bfr[8][2];
#pragma unroll
        for (int ntp = 0; ntp < 4; ntp++) {
            int ncg = (wn >> 3) + ntp * 2 + lnc;
            int chunk = ncg ^ (lk & 7);
            unsigned addr = bs_base + s * 4096 + lk * 256 + chunk * 16;
            unsigned r0, r1, r2, r3;
            asm volatile(
                "ldmatrix.sync.aligned.m8n8.x4.trans.shared.b16 {%0,%1,%2,%3}, [%4];"
                : "=r"(r0), "=r"(r1), "=r"(r2), "=r"(r3) : "r"(addr));
            bfr[ntp * 2    ][0] = r0;
            bfr[ntp * 2    ][1] = r1;
            bfr[ntp * 2 + 1][0] = r2;
            bfr[ntp * 2 + 1][1] = r3;
        }
#pragma unroll
        for (int mt = 0; mt < 2; mt++)
#pragma unroll
            for (int nt = 0; nt < 8; nt++)
                mma_f16(acc[mt][nt], afr[mt], bfr[nt]);
    }

#pragma unroll
    for (int nt = 0; nt < 8; nt++) {
        const int cc = col0 + wn + nt * 8 + 2 * tig;
        float2 bv = *(const float2*)&bias[cc];
#pragma unroll
        for (int mt = 0; mt < 2; mt++) {
            int r0 = row0 + wm + mt * 16 + gid;
#pragma unroll
            for (int half_ = 0; half_ < 2; half_++) {
                int rr = r0 + half_ * 8;
                float vx = acc[mt][nt][half_ * 2 + 0] + bv.x;
                float vy = acc[mt][nt][half_ * 2 + 1] + bv.y;
                if (mode == 0) {
                    *(__half2*)&Ch[(long)rr * N + cc] = __floats2half2_rn(vx, vy);
                } else if (mode == 1) {
                    float2 rrv = *(const float2*)&R[(long)rr * N + cc];
                    *(float2*)&Cf[(long)rr * N + cc] = make_float2(vx + rrv.x, vy + rrv.y);
                } else {
                    float t0 = vx, t1 = vy;
                    vx = 0.5f * t0 * (1.f + tanhf(0.7978845608028654f * (t0 + 0.044715f * t0 * t0 * t0)));
                    vy = 0.5f * t1 * (1.f + tanhf(0.7978845608028654f * (t1 + 0.044715f * t1 * t1 * t1)));
                    *(__half2*)&Ch[(long)rr * N + cc] = __floats2half2_rn(vx, vy);
                }
            }
        }
    }
}

// ---------------- layernorm over H=768 ----------------
__global__ void __launch_bounds__(256)
ln_kernel(const float* __restrict__ in, const float* __restrict__ g,
          const float* __restrict__ b, float* __restrict__ out, __half* __restrict__ outh)
{
    const int row = blockIdx.x;
    const float* x = in + (long)row * HH;
    float v0[3];
    float s = 0.f, s2 = 0.f;
#pragma unroll
    for (int i = 0; i < 3; i++) {
        float t = x[threadIdx.x + i * 256];
        v0[i] = t; s += t; s2 += t * t;
    }
#pragma unroll
    for (int o = 16; o > 0; o >>= 1) {
        s  += __shfl_xor_sync(0xffffffffu, s, o);
        s2 += __shfl_xor_sync(0xffffffffu, s2, o);
    }
    __shared__ float red0[8], red1[8];
    int w = threadIdx.x >> 5;
    if ((threadIdx.x & 31) == 0) { red0[w] = s; red1[w] = s2; }
    __syncthreads();
    if (threadIdx.x < 32) {
        s  = (threadIdx.x < 8) ? red0[threadIdx.x] : 0.f;
        s2 = (threadIdx.x < 8) ? red1[threadIdx.x] : 0.f;
#pragma unroll
        for (int o = 4; o > 0; o >>= 1) {
            s  += __shfl_xor_sync(0xffffffffu, s, o);
            s2 += __shfl_xor_sync(0xffffffffu, s2, o);
        }
        if (threadIdx.x == 0) { red0[0] = s; red1[0] = s2; }
    }
    __syncthreads();
    float mean = red0[0] * (1.f / HH);
    float var  = red1[0] * (1.f / HH) - mean * mean;
    float rstd = rsqrtf(var + 1e-5f);
#pragma unroll
    for (int i = 0; i < 3; i++) {
        int c = threadIdx.x + i * 256;
        float val = (v0[i] - mean) * rstd * g[c] + b[c];
        out [(long)row * HH + c] = val;
        outh[(long)row * HH + c] = __float2half(val);
    }
}

// ---------------- banded attention via mma: 64-query CTAs, 128 thr ----------------
// grid (SS/64=32, 12, 2) = 768 CTAs; warp w -> query rows [n*64 + w*16, +16)
// 6 key tiles of 64: 5 band tiles (320 keys at n*64-128) + global tile (keys 0..15)
__global__ void __launch_bounds__(128)
band_attn_kernel(const __half* __restrict__ qkv, __half* __restrict__ o)
{
    const int n = blockIdx.x, h = blockIdx.y, b = blockIdx.z;
    const int tid  = threadIdx.x;
    const int w    = tid >> 5;
    const int lane = tid & 31;
    const int gid  = lane >> 2;
    const int tig  = lane & 3;

    __shared__ __align__(16) char smem[2][2][64 * 128];
    const unsigned smem_base = (unsigned)__cvta_generic_to_shared(&smem[0][0][0]);

    const int s_q0 = n * 64 + w * 16 + gid;
    const int s_q1 = s_q0 + 8;

    unsigned qf[4][4];
    {
        const __half* q0 = qkv + ((long)(b * SS + s_q0) * QKVW + h * DD);
        const __half* q1 = qkv + ((long)(b * SS + s_q1) * QKVW + h * DD);
#pragma unroll
        for (int kk = 0; kk < 4; kk++) {
            int d0 = kk * 16 + 2 * tig;
            qf[kk][0] = *(const unsigned*)(q0 + d0);
            qf[kk][1] = *(const unsigned*)(q1 + d0);
            qf[kk][2] = *(const unsigned*)(q0 + d0 + 8);
            qf[kk][3] = *(const unsigned*)(q1 + d0 + 8);
        }
    }

    float m0 = -1e30f, m1 = -1e30f, l0 = 0.f, l1 = 0.f;
    float accO[8][4];
#pragma unroll
    for (int dt = 0; dt < 8; dt++)
#pragma unroll
        for (int u = 0; u < 4; u++) accO[dt][u] = 0.f;

    // tiles 0..4: band keys from n*64-128; tile 5: global keys 0..15 (rows 16..63 padded)
    auto fill = [&](int t) {
        const int buf = t & 1;
#pragma unroll
        for (int i = 0; i < 8; i++) {
            int g = tid + i * 128;
            int tensor = g >> 9;
            int within = g & 511;
            int row = within >> 3;
            int c   = within & 7;
            int p  = (t == 5) ? row : (n * 64 - 2 * 64 + t * 64 + row);
            int pc = min(max(p, 0), SS - 1);
            const __half* src = qkv + ((long)(b * SS + pc) * QKVW + (tensor ? 2 * HH : HH) + h * DD + c * 8);
            unsigned dst = smem_base + buf * 16384 + tensor * 8192 + row * 128 + (((unsigned)(c ^ (row & 7))) << 4);
            cp16(dst, src);
        }
        asm volatile("cp.async.commit_group;\n");
    };

    fill(0);

    for (int t = 0; t < 6; t++) {
        const int buf = t & 1;
        if (t + 1 < 6) {
            fill(t + 1);
            asm volatile("cp.async.wait_group 1;\n" ::: "memory");
        } else {
            asm volatile("cp.async.wait_group 0;\n" ::: "memory");
        }
        __syncthreads();

        const unsigned kb = smem_base + buf * 16384;
        const unsigned vb = kb + 8192;

        float s[8][4];
#pragma unroll
        for (int ng = 0; ng < 8; ng++)
#pragma unroll
            for (int u = 0; u < 4; u++) s[ng][u] = 0.f;

#pragma unroll
        for (int ng = 0; ng < 8; ng++) {
#pragma unroll
            for (int kp = 0; kp < 2; kp++) {
                int row = ng * 8 + (lane & 7);
                int ci  = kp * 4 + (lane >> 3);
                unsigned addr = kb + row * 128 + (((unsigned)(ci ^ (row & 7))) << 4);
                unsigned r0, r1, r2, r3;
                asm volatile(
                    "ldmatrix.sync.aligned.m8n8.x4.shared.b16 {%0,%1,%2,%3}, [%4];"
                    : "=r"(r0), "=r"(r1), "=r"(r2), "=r"(r3) : "r"(addr));
                unsigned bf0[2] = {r0, r1};
                unsigned bf1[2] = {r2, r3};
                mma_f16(s[ng], qf[kp * 2],     bf0);
                mma_f16(s[ng], qf[kp * 2 + 1], bf1);
            }
        }

        const int p00 = (t == 5) ? 0 : (n * 64 - 128 + t * 64);
#pragma unroll
        for (int ng = 0; ng < 8; ng++) {
            int k0 = ng * 8 + 2 * tig;
            int p0v = p00 + k0;
            int p1v = p0v + 1;
            bool v00, v01, v10, v11;
            if (t == 5) {
                v00 = v10 = (k0 < GT);
                v01 = v11 = (k0 + 1 < GT);
            } else {
                bool base0 = (p0v >= GT) && (p0v < SS);
                bool base1 = (p1v >= GT) && (p1v < SS);
                v00 = base0 && (abs(p0v - s_q0) <= CW);
                v10 = base0 && (abs(p0v - s_q1) <= CW);
                v01 = base1 && (abs(p1v - s_q0) <= CW);
                v11 = base1 && (abs(p1v - s_q1) <= CW);
            }
            if (!v00) s[ng][0] = -1e30f;
            if (!v01) s[ng][1] = -1e30f;
            if (!v10) s[ng][2] = -1e30f;
            if (!v11) s[ng][3] = -1e30f;
        }

        float t0 = -1e30f, t1 = -1e30f;
#pragma unroll
        for (int ng = 0; ng < 8; ng++) {
            t0 = fmaxf(t0, fmaxf(s[ng][0], s[ng][1]));
            t1 = fmaxf(t1, fmaxf(s[ng][2], s[ng][3]));
        }
        t0 = fmaxf(t0, __shfl_xor_sync(0xffffffffu, t0, 1));
        t0 = fmaxf(t0, __shfl_xor_sync(0xffffffffu, t0, 2));
        t1 = fmaxf(t1, __shfl_xor_sync(0xffffffffu, t1, 1));
        t1 = fmaxf(t1, __shfl_xor_sync(0xffffffffu, t1, 2));

        float mn0 = fmaxf(m0, t0), mn1 = fmaxf(m1, t1);
        float al0 = __expf(m0 - mn0), al1 = __expf(m1 - mn1);
        l0 *= al0; l1 *= al1;
#pragma unroll
        for (int dt = 0; dt < 8; dt++) {
            accO[dt][0] *= al0; accO[dt][1] *= al0;
            accO[dt][2] *= al1; accO[dt][3] *= al1;
        }

        unsigned ph[8][2];
#pragma unroll
        for (int ng = 0; ng < 8; ng++) {
            float p0 = (s[ng][0] < -1e29f) ? 0.f : __expf(s[ng][0] - mn0);
            float p1 = (s[ng][1] < -1e29f) ? 0.f : __expf(s[ng][1] - mn0);
            float p2 = (s[ng][2] < -1e29f) ? 0.f : __expf(s[ng][2] - mn1);
            float p3 = (s[ng][3] < -1e29f) ? 0.f : __expf(s[ng][3] - mn1);
            l0 += p0 + p1;
            l1 += p2 + p3;
            __half2 h01 = __floats2half2_rn(p0, p1);
            __half2 h23 = __floats2half2_rn(p2, p3);
            ph[ng][0] = *reinterpret_cast<unsigned*>(&h01);
            ph[ng][1] = *reinterpret_cast<unsigned*>(&h23);
        }
        m0 = mn0; m1 = mn1;

        const int lsel = lane >> 3;
        const int lk   = (lsel & 1) * 8 + (lane & 7);
        const int lnc  = lsel >> 1;
#pragma unroll
        for (int kk = 0; kk < 4; kk++) {
            unsigned af[4] = { ph[2 * kk][0], ph[2 * kk][1], ph[2 * kk + 1][0], ph[2 * kk + 1][1] };
#pragma unroll
            for (int dp = 0; dp < 4; dp++) {
                int row = kk * 16 + lk;
                int ci  = (dp * 2 + lnc) ^ (row & 7);
                unsigned addr = vb + row * 128 + (((unsigned)ci) << 4);
                unsigned r0, r1, r2, r3;
                asm volatile(
                    "ldmatrix.sync.aligned.m8n8.x4.trans.shared.b16 {%0,%1,%2,%3}, [%4];"
                    : "=r"(r0), "=r"(r1), "=r"(r2), "=r"(r3) : "r"(addr));
                unsigned b0[2] = {r0, r1};
                unsigned b1[2] = {r2, r3};
                mma_f16(accO[dp * 2],     af, b0);
                mma_f16(accO[dp * 2 + 1], af, b1);
            }
        }
        __syncthreads();
    }

    l0 += __shfl_xor_sync(0xffffffffu, l0, 1);
    l0 += __shfl_xor_sync(0xffffffffu, l0, 2);
    l1 += __shfl_xor_sync(0xffffffffu, l1, 1);
    l1 += __shfl_xor_sync(0xffffffffu, l1, 2);
    float i0 = 1.f / l0, i1 = 1.f / l1;

    __half* o0 = o + ((long)(b * SS + s_q0) * HH + h * DD);
    __half* o1 = o + ((long)(b * SS + s_q1) * HH + h * DD);
#pragma unroll
    for (int dt = 0; dt < 8; dt++) {
        int d0 = dt * 8 + 2 * tig;
        *(__half2*)(o0 + d0) = __floats2half2_rn(accO[dt][0] * i0, accO[dt][1] * i0);
        *(__half2*)(o1 + d0) = __floats2half2_rn(accO[dt][2] * i1, accO[dt][3] * i1);
    }
}

// ---------------- global-query attention (fp16 qkv) ----------------
__global__ void __launch_bounds__(128)
glob_attn_kernel(const __half* __restrict__ qkv, __half* __restrict__ o)
{
    const int g = blockIdx.x, h = blockIdx.y, b = blockIdx.z;
    const int tid = threadIdx.x;

    __shared__ float qs[DD];
    __shared__ float sc[SS];
    __shared__ float red[4];
    __shared__ float part[4][DD];

    if (tid < DD) qs[tid] = __half2float(qkv[(long)(b * SS + g) * QKVW + h * DD + tid]);
    __syncthreads();

    float lm = -1e30f;
    for (int s = tid; s < SS; s += 128) {
        const __half* kr = qkv + ((long)(b * SS + s) * QKVW + HH + h * DD);
        float acc = 0.f;
#pragma unroll
        for (int c = 0; c < 8; c++) {
            uint4 raw = *(const uint4*)(kr + c * 8);
            __half2* hp = (__half2*)&raw;
#pragma unroll
            for (int u = 0; u < 4; u++) {
                float2 kf = __half22float2(hp[u]);
                acc += qs[c * 8 + 2 * u] * kf.x + qs[c * 8 + 2 * u + 1] * kf.y;
            }
        }
        sc[s] = acc;
        lm = fmaxf(lm, acc);
    }
#pragma unroll
    for (int off = 16; off > 0; off >>= 1)
        lm = fmaxf(lm, __shfl_xor_sync(0xffffffffu, lm, off));
    if ((tid & 31) == 0) red[tid >> 5] = lm;
    __syncthreads();
    float m = fmaxf(fmaxf(red[0], red[1]), fmaxf(red[2], red[3]));

    float ls = 0.f;
    for (int s = tid; s < SS; s += 128) {
        float e = __expf(sc[s] - m);
        sc[s] = e;
        ls += e;
    }
#pragma unroll
    for (int off = 16; off > 0; off >>= 1)
        ls += __shfl_xor_sync(0xffffffffu, ls, off);
    __syncthreads();
    if ((tid & 31) == 0) red[tid >> 5] = ls;
    __syncthreads();
    float l = red[0] + red[1] + red[2] + red[3];

    const int d2  = (tid & 31) * 2;
    const int grp = tid >> 5;
    float2 acc2 = make_float2(0.f, 0.f);
    const __half* vp = qkv + ((long)(b * SS) * QKVW + 2 * HH + h * DD + d2);
    const int s0 = grp * (SS / 4);
    for (int s = s0; s < s0 + SS / 4; s++) {
        __half2 hv = *(const __half2*)(vp + (long)s * QKVW);
        float2 f = __half22float2(hv);
        acc2.x += sc[s] * f.x;
        acc2.y += sc[s] * f.y;
    }
    part[grp][d2]     = acc2.x;
    part[grp][d2 + 1] = acc2.y;
    __syncthreads();
    if (tid < DD) {
        float inv = 1.f / l;
        float v = (part[0][tid] + part[1][tid] + part[2][tid] + part[3][tid]) * inv;
        o[(long)(b * SS + g) * HH + h * DD + tid] = __float2half(v);
    }
}

// ---------------- pair gather + classifier head ----------------
__global__ void __launch_bounds__(128)
head_kernel(const float* __restrict__ x, const int* __restrict__ pairs,
            const float* __restrict__ Wh, const float* __restrict__ bh,
            float* __restrict__ out)
{
    const int bp = blockIdx.x;
    const int b = bp >> 7;
    const int i = pairs[bp * 2 + 0];
    const int j = pairs[bp * 2 + 1];
    const float* xi = x + (long)(b * SS + i) * HH;
    const float* xj = x + (long)(b * SS + j) * HH;

    float acc[NLC] = {0.f, 0.f, 0.f};
    for (int d = threadIdx.x; d < 2 * HH; d += 128) {
        float e = (d < HH) ? xi[d] : xj[d - HH];
        acc[0] += e * Wh[d * NLC + 0];
        acc[1] += e * Wh[d * NLC + 1];
        acc[2] += e * Wh[d * NLC + 2];
    }
#pragma unroll
    for (int o = 16; o > 0; o >>= 1) {
#pragma unroll
        for (int c = 0; c < NLC; c++)
            acc[c] += __shfl_xor_sync(0xffffffffu, acc[c], o);
    }
    __shared__ float sm[NLC][4];
    int w = threadIdx.x >> 5;
    if ((threadIdx.x & 31) == 0) {
#pragma unroll
        for (int c = 0; c < NLC; c++) sm[c][w] = acc[c];
    }
    __syncthreads();
    if (threadIdx.x < NLC) {
        float s = sm[threadIdx.x][0] + sm[threadIdx.x][1] + sm[threadIdx.x][2] + sm[threadIdx.x][3];
        out[bp * NLC + threadIdx.x] = s + bh[threadIdx.x];
    }
}

// ---------------- host orchestration ----------------
extern "C" void kernel_launch(void* const* d_in, const int* in_sizes, int n_in,
                              void* d_out, int out_size)
{
    const int*   input_ids    = (const int*)  d_in[0];
    const int*   pair_indices = (const int*)  d_in[1];
    const float* emb          = (const float*)d_in[2];
    const float* Wq  = (const float*)d_in[3];
    const float* bq  = (const float*)d_in[4];
    const float* Wk  = (const float*)d_in[5];
    const float* bk  = (const float*)d_in[6];
    const float* Wv  = (const float*)d_in[7];
    const float* bv  = (const float*)d_in[8];
    const float* Wo  = (const float*)d_in[9];
    const float* bo  = (const float*)d_in[10];
    const float* ln1g = (const float*)d_in[11];
    const float* ln1b = (const float*)d_in[12];
    const float* Wf1 = (const float*)d_in[13];
    const float* bf1 = (const float*)d_in[14];
    const float* Wf2 = (const float*)d_in[15];
    const float* bf2 = (const float*)d_in[16];
    const float* ln2g = (const float*)d_in[17];
    const float* ln2b = (const float*)d_in[18];
    const float* Wh  = (const float*)d_in[19];
    const float* bh  = (const float*)d_in[20];
    float* out = (float*)d_out;

    float *x, *tb, *bqkv;
    __half *qkvh, *xh, *o16, *h16, *wbuf;
    cudaGetSymbolAddress((void**)&x,    g_x);
    cudaGetSymbolAddress((void**)&tb,   g_t);
    cudaGetSymbolAddress((void**)&bqkv, g_bqkv);
    cudaGetSymbolAddress((void**)&qkvh, g_qkvh);
    cudaGetSymbolAddress((void**)&xh,   g_xh);
    cudaGetSymbolAddress((void**)&o16,  g_o16);
    cudaGetSymbolAddress((void**)&h16,  g_h16);
    cudaGetSymbolAddress((void**)&wbuf, g_wbuf);

    long nQKV = (long)LL * HH * QKVW;
    int  nHH  = LL * HH * HH;
    int  nFF  = LL * HH * FF;

    const dim3 gQKV(QKVW / GN, MROWS / GM);     // 18 x 32
    const dim3 gFF (FF   / GN, MROWS / GM);     // 24 x 32
    const dim3 gHHs(HH   / GN, MROWS / 64);     //  6 x 64 = 384 CTAs
    const dim3 attnGrid(SS / 64, NHH, BB);      // 32 x 12 x 2 = 768 CTAs
    const dim3 globGrid(GT, NHH, BB);

    // launches 0..3: embed, pack_qkv, pack_bqkv, gemmQKV  (ncu capture = index 3)
    {
        int total = MROWS * HH;
        embed_kernel<<<(total + 255) / 256, 256>>>(input_ids, emb, x, xh);
        pack_qkv_kernel<<<(int)((nQKV / 8 + 255) / 256), 256>>>(Wq, Wk, Wv, wbuf + WQKVOFF);
        pack_bqkv_kernel<<<(LL * QKVW + 255) / 256, 256>>>(bq, bk, bv, bqkv);
    }

    for (int l = 0; l < LL; l++) {
        const __half* wqkv = wbuf + WQKVOFF + (long)l * HH * QKVW;
        const __half* wo   = wbuf + WOOFF   + (long)l * HH * HH;
        const __half* w1   = wbuf + WF1OFF  + (long)l * HH * FF;
        const __half* w2   = wbuf + WF2OFF  + (long)l * FF * HH;

        gemm16_kernel<<<gQKV, 256>>>(xh, wqkv, bqkv + l * QKVW, nullptr, nullptr, qkvh, MROWS, QKVW, HH, 0);

        if (l == 0) {
            f2h_kernel<<<(nHH / 8 + 255) / 256, 256>>>(Wo,  wbuf + WOOFF,  nHH);
            f2h_kernel<<<(nFF / 8 + 255) / 256, 256>>>(Wf1, wbuf + WF1OFF, nFF);
            f2h_kernel<<<(nFF / 8 + 255) / 256, 256>>>(Wf2, wbuf + WF2OFF, nFF);
        }

        band_attn_kernel<<<attnGrid, 128>>>(qkvh, o16);
        glob_attn_kernel<<<globGrid, 128>>>(qkvh, o16);

        gemm16s_kernel<<<gHHs, 128>>>(o16, wo, bo + l * HH, x, tb, nullptr, MROWS, HH, HH, 1);
        ln_kernel<<<MROWS, 256>>>(tb, ln1g + l * HH, ln1b + l * HH, x, xh);

        gemm16_kernel<<<gFF, 256>>>(xh, w1, bf1 + l * FF, nullptr, nullptr, h16, MROWS, FF, HH, 2);
        gemm16s_kernel<<<gHHs, 128>>>(h16, w2, bf2 + l * HH, x, tb, nullptr, MROWS, HH, FF, 1);
        ln_kernel<<<MROWS, 256>>>(tb, ln2g + l * HH, ln2b + l * HH, x, xh);
    }

    head_kernel<<<BB * PP, 128>>>(x, pair_indices, Wh, bh, out);
}